// round 6
// baseline (speedup 1.0000x reference)
#include <cuda_runtime.h>
#include <cuda_bf16.h>
#include <cstdint>

// Problem constants
#define BB 4
#define NN 4096
#define CC 64
#define BN (BB * NN)

#define TARGETF 560.0f
#define MIN_BOXF 5.0f
#define IOU_THRF 0.2f
#define CONF_THRF 0.001f
#define BOX_CONF_THRF 0.01f
#define MAX_WHF 4096.0f

#define CAP 256                    // per-class member cap for fast path
#define WSTRIDE 8                  // mask words per row (CAP/32)

// ------------------------- scratch (static device memory) -------------------
__device__ float4 g_cbox[BN];                      // clipped boxes, orig order
__device__ float  g_key[BN];                       // valid ? conf : -1
__device__ __align__(128) unsigned char g_tag[BN]; // valid ? cls : 255
__device__ float  g_kept[BB * NN * 8];             // kept entries (8 floats)
__device__ int    g_kcnt[BB];

// ------------------------- K0: zero output + counters -----------------------
__global__ void k0_zero(float* out, int n) {
    int i = blockIdx.x * blockDim.x + threadIdx.x;
    if (i < n) out[i] = 0.0f;
    if (i < BB) g_kcnt[i] = 0;
}

// ------------------------- K1: conf / argmax / clip / valid -----------------
__global__ void k1_prepare(const float* __restrict__ boxes,
                           const float* __restrict__ scores,
                           const float* __restrict__ preds) {
    int box  = (blockIdx.x * blockDim.x + threadIdx.x) >> 5;
    int lane = threadIdx.x & 31;
    if (box >= BN) return;

    const float* p = preds + (size_t)box * CC;
    float s = scores[box];

    float v0 = __fmul_rn(p[lane], s);
    float v1 = __fmul_rn(p[lane + 32], s);
    float bv; int bi;
    if (v1 > v0) { bv = v1; bi = lane + 32; } else { bv = v0; bi = lane; }

    #pragma unroll
    for (int o = 16; o > 0; o >>= 1) {
        float ov = __shfl_down_sync(0xffffffffu, bv, o);
        int   oi = __shfl_down_sync(0xffffffffu, bi, o);
        if (ov > bv || (ov == bv && oi < bi)) { bv = ov; bi = oi; }
    }

    if (lane == 0) {
        float4 bx = reinterpret_cast<const float4*>(boxes)[box];
        float x1 = fminf(fmaxf(bx.x, 0.0f), TARGETF);
        float y1 = fminf(fmaxf(bx.y, 0.0f), TARGETF);
        float x2 = fminf(fmaxf(bx.z, 0.0f), TARGETF);
        float y2 = fminf(fmaxf(bx.w, 0.0f), TARGETF);
        float w = __fsub_rn(x2, x1);
        float h = __fsub_rn(y2, y1);
        int valid = (s > BOX_CONF_THRF) && (w > MIN_BOXF) && (h > MIN_BOXF)
                    && (bv > CONF_THRF);
        g_cbox[box] = make_float4(x1, y1, x2, y2);
        g_key[box]  = valid ? bv : -1.0f;
        g_tag[box]  = valid ? (unsigned char)bi : (unsigned char)255;
    }
}

// ------------------------- helpers for register bitonic --------------------
__device__ __forceinline__ unsigned long long kmin(unsigned long long a,
                                                   unsigned long long b) {
    return a < b ? a : b;
}
__device__ __forceinline__ unsigned long long kmax(unsigned long long a,
                                                   unsigned long long b) {
    return a > b ? a : b;
}
__device__ __forceinline__ void stage_j(unsigned long long v[4], int i0,
                                        int lane, int k, int j) {
    if (j >= 4) {
        int m = j >> 2;
        #pragma unroll
        for (int r = 0; r < 4; r++) {
            unsigned long long other = __shfl_xor_sync(0xffffffffu, v[r], m);
            bool up = (((i0 + r) & k) == 0);
            bool keepmin = (((lane & m) == 0) == up);
            v[r] = keepmin ? kmin(v[r], other) : kmax(v[r], other);
        }
    } else if (j == 2) {
        #pragma unroll
        for (int r = 0; r < 2; r++) {
            bool up = (((i0 + r) & k) == 0);
            unsigned long long a = v[r], c = v[r + 2];
            if ((a > c) == up) { v[r] = c; v[r + 2] = a; }
        }
    } else {
        #pragma unroll
        for (int r = 0; r < 4; r += 2) {
            bool up = (((i0 + r) & k) == 0);
            unsigned long long a = v[r], c = v[r + 1];
            if ((a > c) == up) { v[r] = c; v[r + 1] = a; }
        }
    }
}

// ------------------------- K2: per-(batch,class) NMS ------------------------
__global__ void __launch_bounds__(128) k2_nms() {
    int bc   = blockIdx.x;
    int b    = bc >> 6;
    int c    = bc & 63;
    int t    = threadIdx.x;
    int lane = t & 31;
    int wid  = t >> 5;

    __shared__ unsigned long long skey[CAP];                  // 2KB
    __shared__ float sx1[CAP], sy1[CAP], sx2[CAP], sy2[CAP];  // 4KB
    __shared__ float sar[CAP], scf[CAP];                      // 2KB
    __shared__ int   spos[CAP];                               // 1KB
    __shared__ unsigned int smask[CAP * WSTRIDE];             // 8KB
    __shared__ int   flist[NN];                               // 16KB
    __shared__ unsigned char fsup[NN];                        // 4KB (fallback)
    __shared__ int   warp_tot[5];
    __shared__ unsigned int keepw[WSTRIDE];
    __shared__ int   sbase;
    __shared__ float rbk[128]; __shared__ int rbm[128];       // fallback
    __shared__ float bbox[8];  __shared__ int bflag[1];

    // ---- Stage 1: compaction ----
    const uint4* tw = reinterpret_cast<const uint4*>(g_tag + b * NN);
    uint4 wa = tw[t * 2], wb = tw[t * 2 + 1];
    unsigned int cls4 = (unsigned int)c * 0x01010101u;
    unsigned int eq[8];
    eq[0] = __vcmpeq4(wa.x, cls4); eq[1] = __vcmpeq4(wa.y, cls4);
    eq[2] = __vcmpeq4(wa.z, cls4); eq[3] = __vcmpeq4(wa.w, cls4);
    eq[4] = __vcmpeq4(wb.x, cls4); eq[5] = __vcmpeq4(wb.y, cls4);
    eq[6] = __vcmpeq4(wb.z, cls4); eq[7] = __vcmpeq4(wb.w, cls4);
    int cnt = 0;
    #pragma unroll
    for (int w = 0; w < 8; w++) cnt += __popc(eq[w]) >> 3;

    int inc = cnt;
    #pragma unroll
    for (int o = 1; o < 32; o <<= 1) {
        int tmp = __shfl_up_sync(0xffffffffu, inc, o);
        if (lane >= o) inc += tmp;
    }
    if (lane == 31) warp_tot[wid] = inc;
    __syncthreads();
    if (t == 0) {
        int run = 0;
        #pragma unroll
        for (int w = 0; w < 4; w++) { int v = warp_tot[w]; warp_tot[w] = run; run += v; }
        warp_tot[4] = run;
    }
    __syncthreads();
    int off = (inc - cnt) + warp_tot[wid];
    int base = t * 32;
    #pragma unroll
    for (int w = 0; w < 8; w++) {
        #pragma unroll
        for (int q = 0; q < 4; q++)
            if ((eq[w] >> (8 * q)) & 1u) flist[off++] = base + w * 4 + q;
    }
    __syncthreads();
    int M = warp_tot[4];
    if (M == 0) return;

    float offc = (float)c * MAX_WHF;   // exact in fp32

    if (M <= CAP) {
        // ---- Stage 2: stable sort by (conf desc, idx asc) ----
        if (M <= 128) {
            if (t < 128) {
                unsigned long long kv = ~0ull;
                if (t < M) {
                    int idx = flist[t];
                    unsigned int x = __float_as_uint(g_key[b * NN + idx]);
                    x = (x & 0x80000000u) ? ~x : (x | 0x80000000u);
                    kv = ((unsigned long long)(~x) << 32) | (unsigned int)idx;
                }
                skey[t] = kv;
            }
            __syncthreads();
            if (wid == 0) {
                unsigned long long v[4];
                int i0 = lane << 2;
                #pragma unroll
                for (int r = 0; r < 4; r++) v[r] = skey[i0 + r];
                #pragma unroll
                for (int k = 2; k <= 128; k <<= 1)
                    for (int j = k >> 1; j >= 1; j >>= 1)
                        stage_j(v, i0, lane, k, j);
                #pragma unroll
                for (int r = 0; r < 4; r++) skey[i0 + r] = v[r];
            }
            __syncthreads();
        } else {
            int P = CAP;
            for (int m = t; m < M; m += 128) {
                int idx = flist[m];
                unsigned int x = __float_as_uint(g_key[b * NN + idx]);
                x = (x & 0x80000000u) ? ~x : (x | 0x80000000u);
                skey[m] = ((unsigned long long)(~x) << 32) | (unsigned int)idx;
            }
            for (int m = M + t; m < P; m += 128) skey[m] = ~0ull;
            __syncthreads();
            for (int k = 2; k <= P; k <<= 1) {
                for (int j = k >> 1; j > 0; j >>= 1) {
                    for (int p = t; p < (P >> 1); p += 128) {
                        int i   = ((p & ~(j - 1)) << 1) | (p & (j - 1));
                        int ixj = i | j;
                        bool up = ((i & k) == 0);
                        unsigned long long a = skey[i], d = skey[ixj];
                        if ((a > d) == up) { skey[i] = d; skey[ixj] = a; }
                    }
                    __syncthreads();
                }
            }
        }

        // ---- Stage 3: unpack + gather member boxes into smem ----
        for (int m = t; m < M; m += 128) {
            int idx = (int)(skey[m] & 0xffffffffull);
            spos[m] = idx;
            scf[m]  = g_key[b * NN + idx];
            float4 bx = g_cbox[b * NN + idx];
            sx1[m] = bx.x; sy1[m] = bx.y; sx2[m] = bx.z; sy2[m] = bx.w;
            float ox1 = __fadd_rn(bx.x, offc), oy1 = __fadd_rn(bx.y, offc);
            float ox2 = __fadd_rn(bx.z, offc), oy2 = __fadd_rn(bx.w, offc);
            sar[m] = __fmul_rn(__fsub_rn(ox2, ox1), __fsub_rn(oy2, oy1));
        }
        __syncthreads();

        // ---- Stage 4: pairwise IoU>thr bit-matrix ----
        int W = (M + 31) >> 5;
        for (int i = wid; i < M; i += 4) {
            float ix1 = __fadd_rn(sx1[i], offc), iy1 = __fadd_rn(sy1[i], offc);
            float ix2 = __fadd_rn(sx2[i], offc), iy2 = __fadd_rn(sy2[i], offc);
            float ai  = sar[i];
            for (int cw = 0; cw < W; cw++) {
                int j = cw * 32 + lane;
                bool s = false;
                if (j < M && j > i) {
                    float jx1 = __fadd_rn(sx1[j], offc), jy1 = __fadd_rn(sy1[j], offc);
                    float jx2 = __fadd_rn(sx2[j], offc), jy2 = __fadd_rn(sy2[j], offc);
                    float aj  = sar[j];
                    float ltx = fmaxf(ix1, jx1), lty = fmaxf(iy1, jy1);
                    float rbx = fminf(ix2, jx2), rby = fminf(iy2, jy2);
                    float w = fmaxf(__fsub_rn(rbx, ltx), 0.0f);
                    float h = fmaxf(__fsub_rn(rby, lty), 0.0f);
                    float inter = __fmul_rn(w, h);
                    float denom = __fadd_rn(__fsub_rn(__fadd_rn(ai, aj), inter), 1e-9f);
                    s = __fdiv_rn(inter, denom) > IOU_THRF;
                }
                unsigned int bal = __ballot_sync(0xffffffffu, s);
                if (lane == 0) smask[i * WSTRIDE + cw] = bal;
            }
        }
        __syncthreads();

        // ---- Stage 5a: keep-mask scan (thread 0, no globals in loop) ----
        if (t == 0) {
            unsigned int sup[WSTRIDE], keep[WSTRIDE];
            #pragma unroll
            for (int w = 0; w < WSTRIDE; w++) { sup[w] = 0; keep[w] = 0; }
            int nk = 0;
            for (int i = 0; i < M; i++) {
                if ((sup[i >> 5] >> (i & 31)) & 1u) continue;
                keep[i >> 5] |= (1u << (i & 31));
                nk++;
                for (int w = 0; w < W; w++) sup[w] |= smask[i * WSTRIDE + w];
            }
            #pragma unroll
            for (int w = 0; w < WSTRIDE; w++) keepw[w] = keep[w];
            sbase = atomicAdd(&g_kcnt[b], nk);
        }
        __syncthreads();

        // ---- Stage 5b: parallel scatter of kept entries ----
        int kb = sbase;
        for (int m = t; m < M; m += 128) {
            if ((keepw[m >> 5] >> (m & 31)) & 1u) {
                int pre = __popc(keepw[m >> 5] & ((1u << (m & 31)) - 1u));
                for (int w = 0; w < (m >> 5); w++) pre += __popc(keepw[w]);
                float* kp = g_kept + ((size_t)b * NN + kb + pre) * 8;
                kp[0] = sx1[m]; kp[1] = sy1[m]; kp[2] = sx2[m]; kp[3] = sy2[m];
                kp[4] = scf[m]; kp[5] = (float)c; kp[6] = (float)spos[m];
                kp[7] = 0.0f;
            }
        }
        return;
    }

    // ---- Fallback (M > CAP): selection-based greedy, correct but slow ------
    for (int m = t; m < M; m += 128) fsup[m] = 0;
    __syncthreads();
    for (;;) {
        float bk = -2.0f; int bm = -1; int bidx = 0x7fffffff;
        for (int m = t; m < M; m += 128) {
            if (fsup[m]) continue;
            int idx = flist[m];
            float kf = g_key[b * NN + idx];
            if (kf > bk || (kf == bk && idx < bidx)) { bk = kf; bm = m; bidx = idx; }
        }
        rbk[t] = bk; rbm[t] = bm;
        __syncthreads();
        if (t == 0) {
            float gbk = -2.0f; int gbm = -1; int gbidx = 0x7fffffff;
            for (int q = 0; q < 128; q++) {
                int m = rbm[q];
                if (m < 0) continue;
                int idx = flist[m];
                if (rbk[q] > gbk || (rbk[q] == gbk && idx < gbidx)) {
                    gbk = rbk[q]; gbm = m; gbidx = idx;
                }
            }
            bflag[0] = gbm;
            if (gbm >= 0) {
                fsup[gbm] = 1;
                float4 bx = g_cbox[b * NN + gbidx];
                int slot = atomicAdd(&g_kcnt[b], 1);
                float* kp = g_kept + ((size_t)b * NN + slot) * 8;
                kp[0] = bx.x; kp[1] = bx.y; kp[2] = bx.z; kp[3] = bx.w;
                kp[4] = gbk; kp[5] = (float)c; kp[6] = (float)gbidx; kp[7] = 0.0f;
                float ox1 = __fadd_rn(bx.x, offc), oy1 = __fadd_rn(bx.y, offc);
                float ox2 = __fadd_rn(bx.z, offc), oy2 = __fadd_rn(bx.w, offc);
                bbox[0] = ox1; bbox[1] = oy1; bbox[2] = ox2; bbox[3] = oy2;
                bbox[4] = __fmul_rn(__fsub_rn(ox2, ox1), __fsub_rn(oy2, oy1));
            }
        }
        __syncthreads();
        if (bflag[0] < 0) break;
        float ix1 = bbox[0], iy1 = bbox[1], ix2 = bbox[2], iy2 = bbox[3];
        float ai = bbox[4];
        for (int m = t; m < M; m += 128) {
            if (fsup[m]) continue;
            int idx = flist[m];
            float4 bx = g_cbox[b * NN + idx];
            float jx1 = __fadd_rn(bx.x, offc), jy1 = __fadd_rn(bx.y, offc);
            float jx2 = __fadd_rn(bx.z, offc), jy2 = __fadd_rn(bx.w, offc);
            float aj  = __fmul_rn(__fsub_rn(jx2, jx1), __fsub_rn(jy2, jy1));
            float ltx = fmaxf(ix1, jx1), lty = fmaxf(iy1, jy1);
            float rbx = fminf(ix2, jx2), rby = fminf(iy2, jy2);
            float w = fmaxf(__fsub_rn(rbx, ltx), 0.0f);
            float h = fmaxf(__fsub_rn(rby, lty), 0.0f);
            float inter = __fmul_rn(w, h);
            float denom = __fadd_rn(__fsub_rn(__fadd_rn(ai, aj), inter), 1e-9f);
            if (__fdiv_rn(inter, denom) > IOU_THRF) fsup[m] = 1;
        }
        __syncthreads();
    }
}

// ------------------------- K3: rank + scatter to output ---------------------
// One THREAD per kept entry; each block sweeps the 4096-key smem array ONCE
// with broadcast loads (1 smem transaction serves the whole warp).
// K_j = (ordered(key_j)<<32) | (4095-j);  rank(e) = #{j : K_j > K_e}
__global__ void __launch_bounds__(256) k3_rank(float* __restrict__ out) {
    int b    = blockIdx.y;
    int t    = threadIdx.x;
    int base = blockIdx.x * 256;

    int kc = g_kcnt[b];
    if (base >= kc) return;   // uniform across block

    __shared__ unsigned long long sk[NN];   // 32KB
    const float4* kr = reinterpret_cast<const float4*>(g_key + b * NN);
    #pragma unroll
    for (int f = t; f < NN / 4; f += 256) {
        float4 v = kr[f];
        int j0 = f * 4;
        float vv[4] = {v.x, v.y, v.z, v.w};
        #pragma unroll
        for (int q = 0; q < 4; q++) {
            unsigned int x = __float_as_uint(vv[q]);
            x = (x & 0x80000000u) ? ~x : (x | 0x80000000u);
            sk[j0 + q] = ((unsigned long long)x << 32)
                       | (unsigned int)(NN - 1 - (j0 + q));
        }
    }
    __syncthreads();

    int e = base + t;
    if (e >= kc) return;

    const float4* kp4 = reinterpret_cast<const float4*>(
        g_kept + ((size_t)b * NN + e) * 8);
    float4 ka = kp4[0];      // x1,y1,x2,y2
    float4 kb = kp4[1];      // conf, cls, idx, 0

    unsigned int x = __float_as_uint(kb.x);
    x = (x & 0x80000000u) ? ~x : (x | 0x80000000u);
    unsigned long long Ke = ((unsigned long long)x << 32)
                          | (unsigned int)(NN - 1 - (int)kb.z);

    int cnt = 0;
    const ulonglong2* s2 = reinterpret_cast<const ulonglong2*>(sk);
    #pragma unroll 16
    for (int f = 0; f < NN / 2; f++) {
        ulonglong2 v = s2[f];          // broadcast across warp
        cnt += (v.x > Ke);
        cnt += (v.y > Ke);
    }

    float* o = out + ((size_t)b * NN + cnt) * 6;
    o[0] = ka.x; o[1] = ka.y; o[2] = ka.z; o[3] = ka.w;
    o[4] = kb.x; o[5] = kb.y;
}

// ------------------------- launch -------------------------------------------
extern "C" void kernel_launch(void* const* d_in, const int* in_sizes, int n_in,
                              void* d_out, int out_size) {
    const float *boxes = nullptr, *scores = nullptr, *preds = nullptr;
    for (int i = 0; i < n_in; i++) {
        if (in_sizes[i] == BN * 4)       boxes  = (const float*)d_in[i];
        else if (in_sizes[i] == BN)      scores = (const float*)d_in[i];
        else if (in_sizes[i] == BN * CC) preds  = (const float*)d_in[i];
    }
    float* out = (float*)d_out;

    k0_zero<<<(out_size + 1023) / 1024, 1024>>>(out, out_size);
    k1_prepare<<<(BN * 32) / 1024, 1024>>>(boxes, scores, preds);
    k2_nms<<<BB * CC, 128>>>();
    dim3 g3(16, BB);
    k3_rank<<<g3, 256>>>(out);
}

// round 7
// speedup vs baseline: 1.0005x; 1.0005x over previous
#include <cuda_runtime.h>
#include <cuda_bf16.h>
#include <cstdint>

// Problem constants
#define BB 4
#define NN 4096
#define CC 64
#define BN (BB * NN)

#define TARGETF 560.0f
#define MIN_BOXF 5.0f
#define IOU_THRF 0.2f
#define CONF_THRF 0.001f
#define BOX_CONF_THRF 0.01f
#define MAX_WHF 4096.0f

#define CAP 256                    // per-class member cap for fast path
#define WSTRIDE 8                  // mask words per row (CAP/32)

// ------------------------- scratch (static device memory) -------------------
__device__ float4 g_cbox[BN];                      // clipped boxes, orig order
__device__ float  g_key[BN];                       // valid ? conf : -1
__device__ __align__(128) unsigned char g_tag[BN]; // valid ? cls : 255
__device__ float  g_kept[BB * NN * 8];             // kept entries (8 floats)
__device__ int    g_kcnt[BB];
__device__ int    g_rank[BN];                      // orig idx -> sorted rank

// ------------------------- K0: zero output + counters -----------------------
__global__ void k0_zero(float* out, int n) {
    int i = blockIdx.x * blockDim.x + threadIdx.x;
    if (i < n) out[i] = 0.0f;
    if (i < BB) g_kcnt[i] = 0;
}

// ------------------------- K1: conf / argmax / clip / valid -----------------
__global__ void k1_prepare(const float* __restrict__ boxes,
                           const float* __restrict__ scores,
                           const float* __restrict__ preds) {
    int box  = (blockIdx.x * blockDim.x + threadIdx.x) >> 5;
    int lane = threadIdx.x & 31;
    if (box >= BN) return;

    const float* p = preds + (size_t)box * CC;
    float s = scores[box];

    float v0 = __fmul_rn(p[lane], s);
    float v1 = __fmul_rn(p[lane + 32], s);
    float bv; int bi;
    if (v1 > v0) { bv = v1; bi = lane + 32; } else { bv = v0; bi = lane; }

    #pragma unroll
    for (int o = 16; o > 0; o >>= 1) {
        float ov = __shfl_down_sync(0xffffffffu, bv, o);
        int   oi = __shfl_down_sync(0xffffffffu, bi, o);
        if (ov > bv || (ov == bv && oi < bi)) { bv = ov; bi = oi; }
    }

    if (lane == 0) {
        float4 bx = reinterpret_cast<const float4*>(boxes)[box];
        float x1 = fminf(fmaxf(bx.x, 0.0f), TARGETF);
        float y1 = fminf(fmaxf(bx.y, 0.0f), TARGETF);
        float x2 = fminf(fmaxf(bx.z, 0.0f), TARGETF);
        float y2 = fminf(fmaxf(bx.w, 0.0f), TARGETF);
        float w = __fsub_rn(x2, x1);
        float h = __fsub_rn(y2, y1);
        int valid = (s > BOX_CONF_THRF) && (w > MIN_BOXF) && (h > MIN_BOXF)
                    && (bv > CONF_THRF);
        g_cbox[box] = make_float4(x1, y1, x2, y2);
        g_key[box]  = valid ? bv : -1.0f;
        g_tag[box]  = valid ? (unsigned char)bi : (unsigned char)255;
    }
}

// ------------------------- helpers for register bitonic --------------------
__device__ __forceinline__ unsigned long long kmin(unsigned long long a,
                                                   unsigned long long b) {
    return a < b ? a : b;
}
__device__ __forceinline__ unsigned long long kmax(unsigned long long a,
                                                   unsigned long long b) {
    return a > b ? a : b;
}
__device__ __forceinline__ void stage_j(unsigned long long v[4], int i0,
                                        int lane, int k, int j) {
    if (j >= 4) {
        int m = j >> 2;
        #pragma unroll
        for (int r = 0; r < 4; r++) {
            unsigned long long other = __shfl_xor_sync(0xffffffffu, v[r], m);
            bool up = (((i0 + r) & k) == 0);
            bool keepmin = (((lane & m) == 0) == up);
            v[r] = keepmin ? kmin(v[r], other) : kmax(v[r], other);
        }
    } else if (j == 2) {
        #pragma unroll
        for (int r = 0; r < 2; r++) {
            bool up = (((i0 + r) & k) == 0);
            unsigned long long a = v[r], c = v[r + 2];
            if ((a > c) == up) { v[r] = c; v[r + 2] = a; }
        }
    } else {
        #pragma unroll
        for (int r = 0; r < 4; r += 2) {
            bool up = (((i0 + r) & k) == 0);
            unsigned long long a = v[r], c = v[r + 1];
            if ((a > c) == up) { v[r] = c; v[r + 1] = a; }
        }
    }
}

// ------------------------- K2b: per-batch global key sort -> rank -----------
// Ascending sort of K = (~ordered(score_key)<<32) | idx  == stable descending
// argsort. Epilogue writes inverse permutation g_rank[orig_idx] = position.
__global__ void __launch_bounds__(1024) k2b_sortrank() {
    int b = blockIdx.x;
    __shared__ unsigned long long sk[NN];
    int tid  = threadIdx.x;
    int lane = tid & 31;
    int i0   = ((tid >> 5) << 7) + (lane << 2);   // warp-local 128-elem base

    #pragma unroll
    for (int u = 0; u < 4; u++) {
        int i = tid + u * 1024;
        unsigned int x = __float_as_uint(g_key[b * NN + i]);
        x = (x & 0x80000000u) ? ~x : (x | 0x80000000u);
        sk[i] = ((unsigned long long)(~x) << 32) | (unsigned int)i;
    }
    __syncthreads();

    // Phase A: k = 2..128 entirely in registers
    {
        unsigned long long v[4];
        #pragma unroll
        for (int r = 0; r < 4; r++) v[r] = sk[i0 + r];
        #pragma unroll
        for (int k = 2; k <= 128; k <<= 1)
            for (int j = k >> 1; j >= 1; j >>= 1)
                stage_j(v, i0, lane, k, j);
        #pragma unroll
        for (int r = 0; r < 4; r++) sk[i0 + r] = v[r];
    }
    __syncthreads();

    // Phase B: k = 256..4096
    for (int k = 256; k <= NN; k <<= 1) {
        for (int j = k >> 1; j >= 128; j >>= 1) {
            #pragma unroll 2
            for (int u = 0; u < 2; u++) {
                int p   = tid + u * 1024;
                int i   = ((p & ~(j - 1)) << 1) | (p & (j - 1));
                int ixj = i | j;
                bool up = ((i & k) == 0);
                unsigned long long a = sk[i], c = sk[ixj];
                if ((a > c) == up) { sk[i] = c; sk[ixj] = a; }
            }
            __syncthreads();
        }
        {
            unsigned long long v[4];
            #pragma unroll
            for (int r = 0; r < 4; r++) v[r] = sk[i0 + r];
            #pragma unroll
            for (int j = 64; j >= 1; j >>= 1)
                stage_j(v, i0, lane, k, j);
            #pragma unroll
            for (int r = 0; r < 4; r++) sk[i0 + r] = v[r];
        }
        __syncthreads();
    }

    // Epilogue: inverse permutation
    #pragma unroll
    for (int u = 0; u < 4; u++) {
        int r = tid + u * 1024;
        int n = (int)(sk[r] & 0xffffffffull);
        g_rank[b * NN + n] = r;
    }
}

// ------------------------- K2: per-(batch,class) NMS ------------------------
__global__ void __launch_bounds__(128) k2_nms() {
    int bc   = blockIdx.x;
    int b    = bc >> 6;
    int c    = bc & 63;
    int t    = threadIdx.x;
    int lane = t & 31;
    int wid  = t >> 5;

    __shared__ unsigned long long skey[CAP];                  // 2KB
    __shared__ float sx1[CAP], sy1[CAP], sx2[CAP], sy2[CAP];  // 4KB
    __shared__ float sar[CAP], scf[CAP];                      // 2KB
    __shared__ int   spos[CAP];                               // 1KB
    __shared__ unsigned int smask[CAP * WSTRIDE];             // 8KB
    __shared__ int   flist[NN];                               // 16KB
    __shared__ unsigned char fsup[NN];                        // 4KB (fallback)
    __shared__ int   warp_tot[5];
    __shared__ unsigned int keepw[WSTRIDE];
    __shared__ int   sbase;
    __shared__ float rbk[128]; __shared__ int rbm[128];       // fallback
    __shared__ float bbox[8];  __shared__ int bflag[1];

    // ---- Stage 1: compaction ----
    const uint4* tw = reinterpret_cast<const uint4*>(g_tag + b * NN);
    uint4 wa = tw[t * 2], wb = tw[t * 2 + 1];
    unsigned int cls4 = (unsigned int)c * 0x01010101u;
    unsigned int eq[8];
    eq[0] = __vcmpeq4(wa.x, cls4); eq[1] = __vcmpeq4(wa.y, cls4);
    eq[2] = __vcmpeq4(wa.z, cls4); eq[3] = __vcmpeq4(wa.w, cls4);
    eq[4] = __vcmpeq4(wb.x, cls4); eq[5] = __vcmpeq4(wb.y, cls4);
    eq[6] = __vcmpeq4(wb.z, cls4); eq[7] = __vcmpeq4(wb.w, cls4);
    int cnt = 0;
    #pragma unroll
    for (int w = 0; w < 8; w++) cnt += __popc(eq[w]) >> 3;

    int inc = cnt;
    #pragma unroll
    for (int o = 1; o < 32; o <<= 1) {
        int tmp = __shfl_up_sync(0xffffffffu, inc, o);
        if (lane >= o) inc += tmp;
    }
    if (lane == 31) warp_tot[wid] = inc;
    __syncthreads();
    if (t == 0) {
        int run = 0;
        #pragma unroll
        for (int w = 0; w < 4; w++) { int v = warp_tot[w]; warp_tot[w] = run; run += v; }
        warp_tot[4] = run;
    }
    __syncthreads();
    int off = (inc - cnt) + warp_tot[wid];
    int base = t * 32;
    #pragma unroll
    for (int w = 0; w < 8; w++) {
        #pragma unroll
        for (int q = 0; q < 4; q++)
            if ((eq[w] >> (8 * q)) & 1u) flist[off++] = base + w * 4 + q;
    }
    __syncthreads();
    int M = warp_tot[4];
    if (M == 0) return;

    float offc = (float)c * MAX_WHF;   // exact in fp32

    if (M <= CAP) {
        // ---- Stage 2: stable sort by (conf desc, idx asc) ----
        if (M <= 128) {
            if (t < 128) {
                unsigned long long kv = ~0ull;
                if (t < M) {
                    int idx = flist[t];
                    unsigned int x = __float_as_uint(g_key[b * NN + idx]);
                    x = (x & 0x80000000u) ? ~x : (x | 0x80000000u);
                    kv = ((unsigned long long)(~x) << 32) | (unsigned int)idx;
                }
                skey[t] = kv;
            }
            __syncthreads();
            if (wid == 0) {
                unsigned long long v[4];
                int i0 = lane << 2;
                #pragma unroll
                for (int r = 0; r < 4; r++) v[r] = skey[i0 + r];
                #pragma unroll
                for (int k = 2; k <= 128; k <<= 1)
                    for (int j = k >> 1; j >= 1; j >>= 1)
                        stage_j(v, i0, lane, k, j);
                #pragma unroll
                for (int r = 0; r < 4; r++) skey[i0 + r] = v[r];
            }
            __syncthreads();
        } else {
            int P = CAP;
            for (int m = t; m < M; m += 128) {
                int idx = flist[m];
                unsigned int x = __float_as_uint(g_key[b * NN + idx]);
                x = (x & 0x80000000u) ? ~x : (x | 0x80000000u);
                skey[m] = ((unsigned long long)(~x) << 32) | (unsigned int)idx;
            }
            for (int m = M + t; m < P; m += 128) skey[m] = ~0ull;
            __syncthreads();
            for (int k = 2; k <= P; k <<= 1) {
                for (int j = k >> 1; j > 0; j >>= 1) {
                    for (int p = t; p < (P >> 1); p += 128) {
                        int i   = ((p & ~(j - 1)) << 1) | (p & (j - 1));
                        int ixj = i | j;
                        bool up = ((i & k) == 0);
                        unsigned long long a = skey[i], d = skey[ixj];
                        if ((a > d) == up) { skey[i] = d; skey[ixj] = a; }
                    }
                    __syncthreads();
                }
            }
        }

        // ---- Stage 3: unpack + gather member boxes into smem ----
        for (int m = t; m < M; m += 128) {
            int idx = (int)(skey[m] & 0xffffffffull);
            spos[m] = idx;
            scf[m]  = g_key[b * NN + idx];
            float4 bx = g_cbox[b * NN + idx];
            sx1[m] = bx.x; sy1[m] = bx.y; sx2[m] = bx.z; sy2[m] = bx.w;
            float ox1 = __fadd_rn(bx.x, offc), oy1 = __fadd_rn(bx.y, offc);
            float ox2 = __fadd_rn(bx.z, offc), oy2 = __fadd_rn(bx.w, offc);
            sar[m] = __fmul_rn(__fsub_rn(ox2, ox1), __fsub_rn(oy2, oy1));
        }
        __syncthreads();

        // ---- Stage 4: pairwise IoU>thr bit-matrix ----
        int W = (M + 31) >> 5;
        for (int i = wid; i < M; i += 4) {
            float ix1 = __fadd_rn(sx1[i], offc), iy1 = __fadd_rn(sy1[i], offc);
            float ix2 = __fadd_rn(sx2[i], offc), iy2 = __fadd_rn(sy2[i], offc);
            float ai  = sar[i];
            for (int cw = 0; cw < W; cw++) {
                int j = cw * 32 + lane;
                bool s = false;
                if (j < M && j > i) {
                    float jx1 = __fadd_rn(sx1[j], offc), jy1 = __fadd_rn(sy1[j], offc);
                    float jx2 = __fadd_rn(sx2[j], offc), jy2 = __fadd_rn(sy2[j], offc);
                    float aj  = sar[j];
                    float ltx = fmaxf(ix1, jx1), lty = fmaxf(iy1, jy1);
                    float rbx = fminf(ix2, jx2), rby = fminf(iy2, jy2);
                    float w = fmaxf(__fsub_rn(rbx, ltx), 0.0f);
                    float h = fmaxf(__fsub_rn(rby, lty), 0.0f);
                    float inter = __fmul_rn(w, h);
                    float denom = __fadd_rn(__fsub_rn(__fadd_rn(ai, aj), inter), 1e-9f);
                    s = __fdiv_rn(inter, denom) > IOU_THRF;
                }
                unsigned int bal = __ballot_sync(0xffffffffu, s);
                if (lane == 0) smask[i * WSTRIDE + cw] = bal;
            }
        }
        __syncthreads();

        // ---- Stage 5a: keep-mask scan ----
        if (t == 0) {
            unsigned int sup[WSTRIDE], keep[WSTRIDE];
            #pragma unroll
            for (int w = 0; w < WSTRIDE; w++) { sup[w] = 0; keep[w] = 0; }
            int nk = 0;
            for (int i = 0; i < M; i++) {
                if ((sup[i >> 5] >> (i & 31)) & 1u) continue;
                keep[i >> 5] |= (1u << (i & 31));
                nk++;
                for (int w = 0; w < W; w++) sup[w] |= smask[i * WSTRIDE + w];
            }
            #pragma unroll
            for (int w = 0; w < WSTRIDE; w++) keepw[w] = keep[w];
            sbase = atomicAdd(&g_kcnt[b], nk);
        }
        __syncthreads();

        // ---- Stage 5b: parallel scatter of kept entries ----
        int kb = sbase;
        for (int m = t; m < M; m += 128) {
            if ((keepw[m >> 5] >> (m & 31)) & 1u) {
                int pre = __popc(keepw[m >> 5] & ((1u << (m & 31)) - 1u));
                for (int w = 0; w < (m >> 5); w++) pre += __popc(keepw[w]);
                float* kp = g_kept + ((size_t)b * NN + kb + pre) * 8;
                kp[0] = sx1[m]; kp[1] = sy1[m]; kp[2] = sx2[m]; kp[3] = sy2[m];
                kp[4] = scf[m]; kp[5] = (float)c; kp[6] = (float)spos[m];
                kp[7] = 0.0f;
            }
        }
        return;
    }

    // ---- Fallback (M > CAP): selection-based greedy, correct but slow ------
    for (int m = t; m < M; m += 128) fsup[m] = 0;
    __syncthreads();
    for (;;) {
        float bk = -2.0f; int bm = -1; int bidx = 0x7fffffff;
        for (int m = t; m < M; m += 128) {
            if (fsup[m]) continue;
            int idx = flist[m];
            float kf = g_key[b * NN + idx];
            if (kf > bk || (kf == bk && idx < bidx)) { bk = kf; bm = m; bidx = idx; }
        }
        rbk[t] = bk; rbm[t] = bm;
        __syncthreads();
        if (t == 0) {
            float gbk = -2.0f; int gbm = -1; int gbidx = 0x7fffffff;
            for (int q = 0; q < 128; q++) {
                int m = rbm[q];
                if (m < 0) continue;
                int idx = flist[m];
                if (rbk[q] > gbk || (rbk[q] == gbk && idx < gbidx)) {
                    gbk = rbk[q]; gbm = m; gbidx = idx;
                }
            }
            bflag[0] = gbm;
            if (gbm >= 0) {
                fsup[gbm] = 1;
                float4 bx = g_cbox[b * NN + gbidx];
                int slot = atomicAdd(&g_kcnt[b], 1);
                float* kp = g_kept + ((size_t)b * NN + slot) * 8;
                kp[0] = bx.x; kp[1] = bx.y; kp[2] = bx.z; kp[3] = bx.w;
                kp[4] = gbk; kp[5] = (float)c; kp[6] = (float)gbidx; kp[7] = 0.0f;
                float ox1 = __fadd_rn(bx.x, offc), oy1 = __fadd_rn(bx.y, offc);
                float ox2 = __fadd_rn(bx.z, offc), oy2 = __fadd_rn(bx.w, offc);
                bbox[0] = ox1; bbox[1] = oy1; bbox[2] = ox2; bbox[3] = oy2;
                bbox[4] = __fmul_rn(__fsub_rn(ox2, ox1), __fsub_rn(oy2, oy1));
            }
        }
        __syncthreads();
        if (bflag[0] < 0) break;
        float ix1 = bbox[0], iy1 = bbox[1], ix2 = bbox[2], iy2 = bbox[3];
        float ai = bbox[4];
        for (int m = t; m < M; m += 128) {
            if (fsup[m]) continue;
            int idx = flist[m];
            float4 bx = g_cbox[b * NN + idx];
            float jx1 = __fadd_rn(bx.x, offc), jy1 = __fadd_rn(bx.y, offc);
            float jx2 = __fadd_rn(bx.z, offc), jy2 = __fadd_rn(bx.w, offc);
            float aj  = __fmul_rn(__fsub_rn(jx2, jx1), __fsub_rn(jy2, jy1));
            float ltx = fmaxf(ix1, jx1), lty = fmaxf(iy1, jy1);
            float rbx = fminf(ix2, jx2), rby = fminf(iy2, jy2);
            float w = fmaxf(__fsub_rn(rbx, ltx), 0.0f);
            float h = fmaxf(__fsub_rn(rby, lty), 0.0f);
            float inter = __fmul_rn(w, h);
            float denom = __fadd_rn(__fsub_rn(__fadd_rn(ai, aj), inter), 1e-9f);
            if (__fdiv_rn(inter, denom) > IOU_THRF) fsup[m] = 1;
        }
        __syncthreads();
    }
}

// ------------------------- K3: O(1) rank lookup + scatter -------------------
__global__ void __launch_bounds__(256) k3_scatter(float* __restrict__ out) {
    int b = blockIdx.y;
    int e = blockIdx.x * 256 + threadIdx.x;
    if (e >= g_kcnt[b]) return;

    const float4* kp4 = reinterpret_cast<const float4*>(
        g_kept + ((size_t)b * NN + e) * 8);
    float4 ka = kp4[0];      // x1,y1,x2,y2
    float4 kb = kp4[1];      // conf, cls, idx, 0

    int rank = g_rank[b * NN + (int)kb.z];
    float* o = out + ((size_t)b * NN + rank) * 6;
    o[0] = ka.x; o[1] = ka.y; o[2] = ka.z; o[3] = ka.w;
    o[4] = kb.x; o[5] = kb.y;
}

// ------------------------- launch -------------------------------------------
extern "C" void kernel_launch(void* const* d_in, const int* in_sizes, int n_in,
                              void* d_out, int out_size) {
    const float *boxes = nullptr, *scores = nullptr, *preds = nullptr;
    for (int i = 0; i < n_in; i++) {
        if (in_sizes[i] == BN * 4)       boxes  = (const float*)d_in[i];
        else if (in_sizes[i] == BN)      scores = (const float*)d_in[i];
        else if (in_sizes[i] == BN * CC) preds  = (const float*)d_in[i];
    }
    float* out = (float*)d_out;

    k0_zero<<<(out_size + 1023) / 1024, 1024>>>(out, out_size);
    k1_prepare<<<(BN * 32) / 1024, 1024>>>(boxes, scores, preds);
    k2b_sortrank<<<BB, 1024>>>();
    k2_nms<<<BB * CC, 128>>>();
    dim3 g3(16, BB);
    k3_scatter<<<g3, 256>>>(out);
}

// round 8
// speedup vs baseline: 1.2300x; 1.2294x over previous
#include <cuda_runtime.h>
#include <cuda_bf16.h>
#include <cstdint>

// Problem constants
#define BB 4
#define NN 4096
#define CC 64
#define BN (BB * NN)
#define CHUNK 512
#define NCH (NN / CHUNK)          // 8 chunks per batch

#define TARGETF 560.0f
#define MIN_BOXF 5.0f
#define IOU_THRF 0.2f
#define CONF_THRF 0.001f
#define BOX_CONF_THRF 0.01f
#define MAX_WHF 4096.0f

#define CAP 256                    // per-class member cap for fast path
#define WSTRIDE 8                  // mask words per row (CAP/32)

// ------------------------- scratch (static device memory) -------------------
__device__ float4 g_cbox[BN];                      // clipped boxes, orig order
__device__ float  g_key[BN];                       // valid ? conf : -1
__device__ __align__(128) unsigned char g_tag[BN]; // valid ? cls : 255
__device__ unsigned long long g_ck[BN];            // sorted key chunks
__device__ float4 g_sbox[BN];                      // boxes in sorted order
__device__ float  g_sconf[BN];                     // conf in sorted order
__device__ __align__(128) unsigned char g_stag[BN];// tags in sorted order

// ------------------------- K0: zero output ----------------------------------
__global__ void k0_zero(float* out, int n) {
    int i = blockIdx.x * blockDim.x + threadIdx.x;
    if (i < n) out[i] = 0.0f;
}

// ------------------------- K1: conf / argmax / clip / valid -----------------
__global__ void k1_prepare(const float* __restrict__ boxes,
                           const float* __restrict__ scores,
                           const float* __restrict__ preds) {
    int box  = (blockIdx.x * blockDim.x + threadIdx.x) >> 5;
    int lane = threadIdx.x & 31;
    if (box >= BN) return;

    const float* p = preds + (size_t)box * CC;
    float s = scores[box];

    float v0 = __fmul_rn(p[lane], s);
    float v1 = __fmul_rn(p[lane + 32], s);
    float bv; int bi;
    if (v1 > v0) { bv = v1; bi = lane + 32; } else { bv = v0; bi = lane; }

    #pragma unroll
    for (int o = 16; o > 0; o >>= 1) {
        float ov = __shfl_down_sync(0xffffffffu, bv, o);
        int   oi = __shfl_down_sync(0xffffffffu, bi, o);
        if (ov > bv || (ov == bv && oi < bi)) { bv = ov; bi = oi; }
    }

    if (lane == 0) {
        float4 bx = reinterpret_cast<const float4*>(boxes)[box];
        float x1 = fminf(fmaxf(bx.x, 0.0f), TARGETF);
        float y1 = fminf(fmaxf(bx.y, 0.0f), TARGETF);
        float x2 = fminf(fmaxf(bx.z, 0.0f), TARGETF);
        float y2 = fminf(fmaxf(bx.w, 0.0f), TARGETF);
        float w = __fsub_rn(x2, x1);
        float h = __fsub_rn(y2, y1);
        int valid = (s > BOX_CONF_THRF) && (w > MIN_BOXF) && (h > MIN_BOXF)
                    && (bv > CONF_THRF);
        g_cbox[box] = make_float4(x1, y1, x2, y2);
        g_key[box]  = valid ? bv : -1.0f;
        g_tag[box]  = valid ? (unsigned char)bi : (unsigned char)255;
    }
}

// ------------------------- register bitonic helpers -------------------------
__device__ __forceinline__ unsigned long long kmin(unsigned long long a,
                                                   unsigned long long b) {
    return a < b ? a : b;
}
__device__ __forceinline__ unsigned long long kmax(unsigned long long a,
                                                   unsigned long long b) {
    return a > b ? a : b;
}
__device__ __forceinline__ void stage_j(unsigned long long v[4], int i0,
                                        int lane, int k, int j) {
    if (j >= 4) {
        int m = j >> 2;
        #pragma unroll
        for (int r = 0; r < 4; r++) {
            unsigned long long other = __shfl_xor_sync(0xffffffffu, v[r], m);
            bool up = (((i0 + r) & k) == 0);
            bool keepmin = (((lane & m) == 0) == up);
            v[r] = keepmin ? kmin(v[r], other) : kmax(v[r], other);
        }
    } else if (j == 2) {
        #pragma unroll
        for (int r = 0; r < 2; r++) {
            bool up = (((i0 + r) & k) == 0);
            unsigned long long a = v[r], c = v[r + 2];
            if ((a > c) == up) { v[r] = c; v[r + 2] = a; }
        }
    } else {
        #pragma unroll
        for (int r = 0; r < 4; r += 2) {
            bool up = (((i0 + r) & k) == 0);
            unsigned long long a = v[r], c = v[r + 1];
            if ((a > c) == up) { v[r] = c; v[r + 1] = a; }
        }
    }
}

// ------------------------- K2a: chunk sort (512 keys/block) -----------------
// Ascending K = (~ordered(score_key)<<32) | idx  == stable desc argsort key.
__global__ void __launch_bounds__(128) k2a_chunksort() {
    int b  = blockIdx.x >> 3;
    int ch = blockIdx.x & 7;
    __shared__ unsigned long long sk[CHUNK];
    int tid  = threadIdx.x;
    int lane = tid & 31;
    int i0   = ((tid >> 5) << 7) + (lane << 2);

    #pragma unroll
    for (int u = 0; u < 4; u++) {
        int i   = tid + u * 128;
        int idx = ch * CHUNK + i;
        unsigned int x = __float_as_uint(g_key[b * NN + idx]);
        x = (x & 0x80000000u) ? ~x : (x | 0x80000000u);
        sk[i] = ((unsigned long long)(~x) << 32) | (unsigned int)idx;
    }
    __syncthreads();

    // Phase A: k = 2..128 in registers
    {
        unsigned long long v[4];
        #pragma unroll
        for (int r = 0; r < 4; r++) v[r] = sk[i0 + r];
        #pragma unroll
        for (int k = 2; k <= 128; k <<= 1)
            for (int j = k >> 1; j >= 1; j >>= 1)
                stage_j(v, i0, lane, k, j);
        #pragma unroll
        for (int r = 0; r < 4; r++) sk[i0 + r] = v[r];
    }
    __syncthreads();

    // Phase B: k = 256, 512
    #pragma unroll
    for (int k = 256; k <= CHUNK; k <<= 1) {
        for (int j = k >> 1; j >= 128; j >>= 1) {
            #pragma unroll 2
            for (int u = 0; u < 2; u++) {
                int p   = tid + u * 128;                     // pair id 0..255
                int i   = ((p & ~(j - 1)) << 1) | (p & (j - 1));
                int ixj = i | j;
                bool up = ((i & k) == 0);
                unsigned long long a = sk[i], c = sk[ixj];
                if ((a > c) == up) { sk[i] = c; sk[ixj] = a; }
            }
            __syncthreads();
        }
        {
            unsigned long long v[4];
            #pragma unroll
            for (int r = 0; r < 4; r++) v[r] = sk[i0 + r];
            #pragma unroll
            for (int j = 64; j >= 1; j >>= 1)
                stage_j(v, i0, lane, k, j);
            #pragma unroll
            for (int r = 0; r < 4; r++) sk[i0 + r] = v[r];
        }
        __syncthreads();
    }

    #pragma unroll
    for (int u = 0; u < 4; u++) {
        int i = tid + u * 128;
        g_ck[b * NN + ch * CHUNK + i] = sk[i];
    }
}

// ------------------------- K2m: rank-merge + scatter sorted arrays ----------
// rank(elem) = pos-in-own-chunk + sum over other chunks of count(key < K).
// Keys are unique (idx in low bits), so strict lower_bound is exact & stable.
__global__ void __launch_bounds__(CHUNK) k2m_merge() {
    int b  = blockIdx.x >> 3;
    int ch = blockIdx.x & 7;
    const unsigned long long* ck = g_ck + b * NN;

    unsigned long long K = ck[ch * CHUNK + threadIdx.x];
    int rank = threadIdx.x;

    int lo[NCH], hi[NCH];
    #pragma unroll
    for (int c2 = 0; c2 < NCH; c2++) { lo[c2] = 0; hi[c2] = (c2 == ch) ? 0 : CHUNK; }

    #pragma unroll
    for (int it = 0; it < 10; it++) {
        #pragma unroll
        for (int c2 = 0; c2 < NCH; c2++) {
            if (lo[c2] < hi[c2]) {
                int mid = (lo[c2] + hi[c2]) >> 1;
                unsigned long long v = ck[c2 * CHUNK + mid];
                if (v < K) lo[c2] = mid + 1; else hi[c2] = mid;
            }
        }
    }
    #pragma unroll
    for (int c2 = 0; c2 < NCH; c2++) rank += lo[c2];

    int idx = (int)(K & 0xffffffffull);
    int d = b * NN + rank;
    int s = b * NN + idx;

    g_sbox[d] = g_cbox[s];
    g_stag[d] = g_tag[s];
    // exact inverse of the total-order map -> original conf bits
    unsigned int up = ~(unsigned int)(K >> 32);
    unsigned int u  = (up & 0x80000000u) ? (up & 0x7fffffffu) : ~up;
    g_sconf[d] = __uint_as_float(u);
}

// ------------------------- K3: per-(batch,class) NMS on sorted arrays -------
// Members arrive in sorted (NMS) order; member position == output row.
// Kept rows are written directly to d_out. No atomics, no extra kernels.
__global__ void __launch_bounds__(128) k3_nms(float* __restrict__ out) {
    int bc   = blockIdx.x;
    int b    = bc >> 6;
    int c    = bc & 63;
    int t    = threadIdx.x;
    int lane = t & 31;
    int wid  = t >> 5;

    __shared__ float sx1[CAP], sy1[CAP], sx2[CAP], sy2[CAP];  // 4KB
    __shared__ float sar[CAP], scf[CAP];                      // 2KB
    __shared__ int   spos[CAP];                               // 1KB
    __shared__ unsigned int smask[CAP * WSTRIDE];             // 8KB
    __shared__ int   flist[NN];                               // 16KB
    __shared__ unsigned char fsup[NN];                        // 4KB (fallback)
    __shared__ int   warp_tot[5];
    __shared__ unsigned int keepw[WSTRIDE];

    // ---- Stage 1: compaction over SORTED tags ----
    const uint4* tw = reinterpret_cast<const uint4*>(g_stag + b * NN);
    uint4 wa = tw[t * 2], wb = tw[t * 2 + 1];
    unsigned int cls4 = (unsigned int)c * 0x01010101u;
    unsigned int eq[8];
    eq[0] = __vcmpeq4(wa.x, cls4); eq[1] = __vcmpeq4(wa.y, cls4);
    eq[2] = __vcmpeq4(wa.z, cls4); eq[3] = __vcmpeq4(wa.w, cls4);
    eq[4] = __vcmpeq4(wb.x, cls4); eq[5] = __vcmpeq4(wb.y, cls4);
    eq[6] = __vcmpeq4(wb.z, cls4); eq[7] = __vcmpeq4(wb.w, cls4);
    int cnt = 0;
    #pragma unroll
    for (int w = 0; w < 8; w++) cnt += __popc(eq[w]) >> 3;

    int inc = cnt;
    #pragma unroll
    for (int o = 1; o < 32; o <<= 1) {
        int tmp = __shfl_up_sync(0xffffffffu, inc, o);
        if (lane >= o) inc += tmp;
    }
    if (lane == 31) warp_tot[wid] = inc;
    __syncthreads();
    if (t == 0) {
        int run = 0;
        #pragma unroll
        for (int w = 0; w < 4; w++) { int v = warp_tot[w]; warp_tot[w] = run; run += v; }
        warp_tot[4] = run;
    }
    __syncthreads();
    int off = (inc - cnt) + warp_tot[wid];
    int base = t * 32;
    #pragma unroll
    for (int w = 0; w < 8; w++) {
        #pragma unroll
        for (int q = 0; q < 4; q++)
            if ((eq[w] >> (8 * q)) & 1u) flist[off++] = base + w * 4 + q;
    }
    __syncthreads();
    int M = warp_tot[4];
    if (M == 0) return;

    float offc = (float)c * MAX_WHF;   // exact in fp32

    if (M <= CAP) {
        // ---- Stage 2: gather member boxes (already in NMS order) ----
        for (int m = t; m < M; m += 128) {
            int pos = flist[m];
            spos[m] = pos;
            scf[m]  = g_sconf[b * NN + pos];
            float4 bx = g_sbox[b * NN + pos];
            sx1[m] = bx.x; sy1[m] = bx.y; sx2[m] = bx.z; sy2[m] = bx.w;
            float ox1 = __fadd_rn(bx.x, offc), oy1 = __fadd_rn(bx.y, offc);
            float ox2 = __fadd_rn(bx.z, offc), oy2 = __fadd_rn(bx.w, offc);
            sar[m] = __fmul_rn(__fsub_rn(ox2, ox1), __fsub_rn(oy2, oy1));
        }
        __syncthreads();

        // ---- Stage 3: pairwise IoU>thr bit-matrix ----
        int W = (M + 31) >> 5;
        for (int i = wid; i < M; i += 4) {
            float ix1 = __fadd_rn(sx1[i], offc), iy1 = __fadd_rn(sy1[i], offc);
            float ix2 = __fadd_rn(sx2[i], offc), iy2 = __fadd_rn(sy2[i], offc);
            float ai  = sar[i];
            for (int cw = 0; cw < W; cw++) {
                int j = cw * 32 + lane;
                bool s = false;
                if (j < M && j > i) {
                    float jx1 = __fadd_rn(sx1[j], offc), jy1 = __fadd_rn(sy1[j], offc);
                    float jx2 = __fadd_rn(sx2[j], offc), jy2 = __fadd_rn(sy2[j], offc);
                    float aj  = sar[j];
                    float ltx = fmaxf(ix1, jx1), lty = fmaxf(iy1, jy1);
                    float rbx = fminf(ix2, jx2), rby = fminf(iy2, jy2);
                    float w = fmaxf(__fsub_rn(rbx, ltx), 0.0f);
                    float h = fmaxf(__fsub_rn(rby, lty), 0.0f);
                    float inter = __fmul_rn(w, h);
                    float denom = __fadd_rn(__fsub_rn(__fadd_rn(ai, aj), inter), 1e-9f);
                    s = __fdiv_rn(inter, denom) > IOU_THRF;
                }
                unsigned int bal = __ballot_sync(0xffffffffu, s);
                if (lane == 0) smask[i * WSTRIDE + cw] = bal;
            }
        }
        __syncthreads();

        // ---- Stage 4a: greedy keep-mask scan (thread 0, smem only) ----
        if (t == 0) {
            unsigned int sup[WSTRIDE], keep[WSTRIDE];
            #pragma unroll
            for (int w = 0; w < WSTRIDE; w++) { sup[w] = 0; keep[w] = 0; }
            for (int i = 0; i < M; i++) {
                if ((sup[i >> 5] >> (i & 31)) & 1u) continue;
                keep[i >> 5] |= (1u << (i & 31));
                for (int w = 0; w < W; w++) sup[w] |= smask[i * WSTRIDE + w];
            }
            #pragma unroll
            for (int w = 0; w < WSTRIDE; w++) keepw[w] = keep[w];
        }
        __syncthreads();

        // ---- Stage 4b: write kept rows DIRECTLY to output at row spos ----
        for (int m = t; m < M; m += 128) {
            if ((keepw[m >> 5] >> (m & 31)) & 1u) {
                float* o = out + ((size_t)b * NN + spos[m]) * 6;
                o[0] = sx1[m]; o[1] = sy1[m]; o[2] = sx2[m]; o[3] = sy2[m];
                o[4] = scf[m]; o[5] = (float)c;
            }
        }
        return;
    }

    // ---- Fallback (M > CAP): in-order greedy (members already sorted) ------
    for (int m = t; m < M; m += 128) fsup[m] = 0;
    __syncthreads();
    for (int i = 0; i < M; i++) {
        if (fsup[i]) { __syncthreads(); continue; }   // uniform across block
        int pos = flist[i];
        float4 bi = g_sbox[b * NN + pos];
        float ix1 = __fadd_rn(bi.x, offc), iy1 = __fadd_rn(bi.y, offc);
        float ix2 = __fadd_rn(bi.z, offc), iy2 = __fadd_rn(bi.w, offc);
        float ai  = __fmul_rn(__fsub_rn(ix2, ix1), __fsub_rn(iy2, iy1));
        if (t == 0) {
            float* o = out + ((size_t)b * NN + pos) * 6;
            o[0] = bi.x; o[1] = bi.y; o[2] = bi.z; o[3] = bi.w;
            o[4] = g_sconf[b * NN + pos];
            o[5] = (float)c;
        }
        for (int j = i + 1 + t; j < M; j += 128) {
            if (fsup[j]) continue;
            int pj = flist[j];
            float4 bj = g_sbox[b * NN + pj];
            float jx1 = __fadd_rn(bj.x, offc), jy1 = __fadd_rn(bj.y, offc);
            float jx2 = __fadd_rn(bj.z, offc), jy2 = __fadd_rn(bj.w, offc);
            float aj  = __fmul_rn(__fsub_rn(jx2, jx1), __fsub_rn(jy2, jy1));
            float ltx = fmaxf(ix1, jx1), lty = fmaxf(iy1, jy1);
            float rbx = fminf(ix2, jx2), rby = fminf(iy2, jy2);
            float w = fmaxf(__fsub_rn(rbx, ltx), 0.0f);
            float h = fmaxf(__fsub_rn(rby, lty), 0.0f);
            float inter = __fmul_rn(w, h);
            float denom = __fadd_rn(__fsub_rn(__fadd_rn(ai, aj), inter), 1e-9f);
            if (__fdiv_rn(inter, denom) > IOU_THRF) fsup[j] = 1;
        }
        __syncthreads();
    }
}

// ------------------------- launch -------------------------------------------
extern "C" void kernel_launch(void* const* d_in, const int* in_sizes, int n_in,
                              void* d_out, int out_size) {
    const float *boxes = nullptr, *scores = nullptr, *preds = nullptr;
    for (int i = 0; i < n_in; i++) {
        if (in_sizes[i] == BN * 4)       boxes  = (const float*)d_in[i];
        else if (in_sizes[i] == BN)      scores = (const float*)d_in[i];
        else if (in_sizes[i] == BN * CC) preds  = (const float*)d_in[i];
    }
    float* out = (float*)d_out;

    k0_zero<<<(out_size + 1023) / 1024, 1024>>>(out, out_size);
    k1_prepare<<<(BN * 32) / 1024, 1024>>>(boxes, scores, preds);
    k2a_chunksort<<<BB * NCH, 128>>>();
    k2m_merge<<<BB * NCH, CHUNK>>>();
    k3_nms<<<BB * CC, 128>>>(out);
}

// round 9
// speedup vs baseline: 1.3231x; 1.0756x over previous
#include <cuda_runtime.h>
#include <cuda_bf16.h>
#include <cstdint>

// Problem constants
#define BB 4
#define NN 4096
#define CC 64
#define BN (BB * NN)
#define CHUNK 512
#define NCH (NN / CHUNK)          // 8 chunks per batch

#define TARGETF 560.0f
#define MIN_BOXF 5.0f
#define IOU_THRF 0.2f
#define CONF_THRF 0.001f
#define BOX_CONF_THRF 0.01f
#define MAX_WHF 4096.0f

#define CAP 256                    // per-class member cap for fast path
#define WSTRIDE 8                  // mask words per row (CAP/32)

// ------------------------- scratch (static device memory) -------------------
__device__ float4 g_cbox[BN];                      // clipped boxes, orig order
__device__ float  g_key[BN];                       // valid ? conf : -1
__device__ __align__(128) unsigned char g_tag[BN]; // valid ? cls : 255
__device__ unsigned long long g_ck[BN];            // sorted key chunks
__device__ float4 g_sbox[BN];                      // boxes in sorted order
__device__ float  g_sconf[BN];                     // conf in sorted order
__device__ __align__(128) unsigned char g_stag[BN];// tags in sorted order

// ------------------------- K1: conf / argmax / clip / valid -----------------
__global__ void k1_prepare(const float* __restrict__ boxes,
                           const float* __restrict__ scores,
                           const float* __restrict__ preds) {
    int box  = (blockIdx.x * blockDim.x + threadIdx.x) >> 5;
    int lane = threadIdx.x & 31;
    if (box >= BN) return;

    const float* p = preds + (size_t)box * CC;
    float s = scores[box];

    float v0 = __fmul_rn(p[lane], s);
    float v1 = __fmul_rn(p[lane + 32], s);
    float bv; int bi;
    if (v1 > v0) { bv = v1; bi = lane + 32; } else { bv = v0; bi = lane; }

    #pragma unroll
    for (int o = 16; o > 0; o >>= 1) {
        float ov = __shfl_down_sync(0xffffffffu, bv, o);
        int   oi = __shfl_down_sync(0xffffffffu, bi, o);
        if (ov > bv || (ov == bv && oi < bi)) { bv = ov; bi = oi; }
    }

    if (lane == 0) {
        float4 bx = reinterpret_cast<const float4*>(boxes)[box];
        float x1 = fminf(fmaxf(bx.x, 0.0f), TARGETF);
        float y1 = fminf(fmaxf(bx.y, 0.0f), TARGETF);
        float x2 = fminf(fmaxf(bx.z, 0.0f), TARGETF);
        float y2 = fminf(fmaxf(bx.w, 0.0f), TARGETF);
        float w = __fsub_rn(x2, x1);
        float h = __fsub_rn(y2, y1);
        int valid = (s > BOX_CONF_THRF) && (w > MIN_BOXF) && (h > MIN_BOXF)
                    && (bv > CONF_THRF);
        g_cbox[box] = make_float4(x1, y1, x2, y2);
        g_key[box]  = valid ? bv : -1.0f;
        g_tag[box]  = valid ? (unsigned char)bi : (unsigned char)255;
    }
}

// ------------------------- register bitonic helpers -------------------------
__device__ __forceinline__ unsigned long long kmin(unsigned long long a,
                                                   unsigned long long b) {
    return a < b ? a : b;
}
__device__ __forceinline__ unsigned long long kmax(unsigned long long a,
                                                   unsigned long long b) {
    return a > b ? a : b;
}
__device__ __forceinline__ void stage_j(unsigned long long v[4], int i0,
                                        int lane, int k, int j) {
    if (j >= 4) {
        int m = j >> 2;
        #pragma unroll
        for (int r = 0; r < 4; r++) {
            unsigned long long other = __shfl_xor_sync(0xffffffffu, v[r], m);
            bool up = (((i0 + r) & k) == 0);
            bool keepmin = (((lane & m) == 0) == up);
            v[r] = keepmin ? kmin(v[r], other) : kmax(v[r], other);
        }
    } else if (j == 2) {
        #pragma unroll
        for (int r = 0; r < 2; r++) {
            bool up = (((i0 + r) & k) == 0);
            unsigned long long a = v[r], c = v[r + 2];
            if ((a > c) == up) { v[r] = c; v[r + 2] = a; }
        }
    } else {
        #pragma unroll
        for (int r = 0; r < 4; r += 2) {
            bool up = (((i0 + r) & k) == 0);
            unsigned long long a = v[r], c = v[r + 1];
            if ((a > c) == up) { v[r] = c; v[r + 1] = a; }
        }
    }
}

// ------------------------- K2a: chunk sort (512 keys/block) -----------------
__global__ void __launch_bounds__(128) k2a_chunksort() {
    int b  = blockIdx.x >> 3;
    int ch = blockIdx.x & 7;
    __shared__ unsigned long long sk[CHUNK];
    int tid  = threadIdx.x;
    int lane = tid & 31;
    int i0   = ((tid >> 5) << 7) + (lane << 2);

    #pragma unroll
    for (int u = 0; u < 4; u++) {
        int i   = tid + u * 128;
        int idx = ch * CHUNK + i;
        unsigned int x = __float_as_uint(g_key[b * NN + idx]);
        x = (x & 0x80000000u) ? ~x : (x | 0x80000000u);
        sk[i] = ((unsigned long long)(~x) << 32) | (unsigned int)idx;
    }
    __syncthreads();

    // Phase A: k = 2..128 in registers
    {
        unsigned long long v[4];
        #pragma unroll
        for (int r = 0; r < 4; r++) v[r] = sk[i0 + r];
        #pragma unroll
        for (int k = 2; k <= 128; k <<= 1)
            for (int j = k >> 1; j >= 1; j >>= 1)
                stage_j(v, i0, lane, k, j);
        #pragma unroll
        for (int r = 0; r < 4; r++) sk[i0 + r] = v[r];
    }
    __syncthreads();

    // Phase B: k = 256, 512
    #pragma unroll
    for (int k = 256; k <= CHUNK; k <<= 1) {
        for (int j = k >> 1; j >= 128; j >>= 1) {
            #pragma unroll 2
            for (int u = 0; u < 2; u++) {
                int p   = tid + u * 128;
                int i   = ((p & ~(j - 1)) << 1) | (p & (j - 1));
                int ixj = i | j;
                bool up = ((i & k) == 0);
                unsigned long long a = sk[i], c = sk[ixj];
                if ((a > c) == up) { sk[i] = c; sk[ixj] = a; }
            }
            __syncthreads();
        }
        {
            unsigned long long v[4];
            #pragma unroll
            for (int r = 0; r < 4; r++) v[r] = sk[i0 + r];
            #pragma unroll
            for (int j = 64; j >= 1; j >>= 1)
                stage_j(v, i0, lane, k, j);
            #pragma unroll
            for (int r = 0; r < 4; r++) sk[i0 + r] = v[r];
        }
        __syncthreads();
    }

    #pragma unroll
    for (int u = 0; u < 4; u++) {
        int i = tid + u * 128;
        g_ck[b * NN + ch * CHUNK + i] = sk[i];
    }
}

// ------------------------- K2m: smem rank-merge + scatter + zero-out --------
// All 4096 batch keys staged to smem (one coalesced load); binary searches
// run at LDS latency with MLP=7. Each thread owns exactly one (batch, rank)
// output row, so it also zeroes that row (k0 deleted).
__global__ void __launch_bounds__(CHUNK) k2m_merge(float* __restrict__ out) {
    int b  = blockIdx.x >> 3;
    int ch = blockIdx.x & 7;
    int tid = threadIdx.x;

    __shared__ unsigned long long sck[NN];          // 32KB
    const unsigned long long* ck = g_ck + b * NN;
    #pragma unroll
    for (int u = 0; u < NCH; u++) sck[tid + u * CHUNK] = ck[tid + u * CHUNK];
    __syncthreads();

    unsigned long long K = sck[ch * CHUNK + tid];
    int rank = tid;

    int lo[NCH], hi[NCH];
    #pragma unroll
    for (int c2 = 0; c2 < NCH; c2++) { lo[c2] = 0; hi[c2] = (c2 == ch) ? 0 : CHUNK; }

    #pragma unroll
    for (int it = 0; it < 10; it++) {
        #pragma unroll
        for (int c2 = 0; c2 < NCH; c2++) {
            if (lo[c2] < hi[c2]) {
                int mid = (lo[c2] + hi[c2]) >> 1;
                unsigned long long v = sck[c2 * CHUNK + mid];
                if (v < K) lo[c2] = mid + 1; else hi[c2] = mid;
            }
        }
    }
    #pragma unroll
    for (int c2 = 0; c2 < NCH; c2++) rank += lo[c2];

    int idx = (int)(K & 0xffffffffull);
    int d = b * NN + rank;
    int s = b * NN + idx;

    // zero this thread's unique output row (poisoned by harness)
    float* o = out + (size_t)d * 6;
    o[0] = 0.0f; o[1] = 0.0f; o[2] = 0.0f;
    o[3] = 0.0f; o[4] = 0.0f; o[5] = 0.0f;

    g_sbox[d] = g_cbox[s];
    g_stag[d] = g_tag[s];
    // exact inverse of the total-order map -> original conf bits
    unsigned int up = ~(unsigned int)(K >> 32);
    unsigned int u  = (up & 0x80000000u) ? (up & 0x7fffffffu) : ~up;
    g_sconf[d] = __uint_as_float(u);
}

// ------------------------- K3: per-(batch,class) NMS on sorted arrays -------
__global__ void __launch_bounds__(128) k3_nms(float* __restrict__ out) {
    int bc   = blockIdx.x;
    int b    = bc >> 6;
    int c    = bc & 63;
    int t    = threadIdx.x;
    int lane = t & 31;
    int wid  = t >> 5;

    __shared__ float sx1[CAP], sy1[CAP], sx2[CAP], sy2[CAP];  // 4KB
    __shared__ float sar[CAP], scf[CAP];                      // 2KB
    __shared__ int   spos[CAP];                               // 1KB
    __shared__ unsigned int smask[CAP * WSTRIDE];             // 8KB
    __shared__ int   flist[NN];                               // 16KB
    __shared__ unsigned char fsup[NN];                        // 4KB (fallback)
    __shared__ int   warp_tot[5];
    __shared__ unsigned int keepw[WSTRIDE];

    // ---- Stage 1: compaction over SORTED tags ----
    const uint4* tw = reinterpret_cast<const uint4*>(g_stag + b * NN);
    uint4 wa = tw[t * 2], wb = tw[t * 2 + 1];
    unsigned int cls4 = (unsigned int)c * 0x01010101u;
    unsigned int eq[8];
    eq[0] = __vcmpeq4(wa.x, cls4); eq[1] = __vcmpeq4(wa.y, cls4);
    eq[2] = __vcmpeq4(wa.z, cls4); eq[3] = __vcmpeq4(wa.w, cls4);
    eq[4] = __vcmpeq4(wb.x, cls4); eq[5] = __vcmpeq4(wb.y, cls4);
    eq[6] = __vcmpeq4(wb.z, cls4); eq[7] = __vcmpeq4(wb.w, cls4);
    int cnt = 0;
    #pragma unroll
    for (int w = 0; w < 8; w++) cnt += __popc(eq[w]) >> 3;

    int inc = cnt;
    #pragma unroll
    for (int o = 1; o < 32; o <<= 1) {
        int tmp = __shfl_up_sync(0xffffffffu, inc, o);
        if (lane >= o) inc += tmp;
    }
    if (lane == 31) warp_tot[wid] = inc;
    __syncthreads();
    if (t == 0) {
        int run = 0;
        #pragma unroll
        for (int w = 0; w < 4; w++) { int v = warp_tot[w]; warp_tot[w] = run; run += v; }
        warp_tot[4] = run;
    }
    __syncthreads();
    int off = (inc - cnt) + warp_tot[wid];
    int base = t * 32;
    #pragma unroll
    for (int w = 0; w < 8; w++) {
        #pragma unroll
        for (int q = 0; q < 4; q++)
            if ((eq[w] >> (8 * q)) & 1u) flist[off++] = base + w * 4 + q;
    }
    __syncthreads();
    int M = warp_tot[4];
    if (M == 0) return;

    float offc = (float)c * MAX_WHF;   // exact in fp32

    if (M <= CAP) {
        // ---- Stage 2: gather member boxes (already in NMS order) ----
        for (int m = t; m < M; m += 128) {
            int pos = flist[m];
            spos[m] = pos;
            scf[m]  = g_sconf[b * NN + pos];
            float4 bx = g_sbox[b * NN + pos];
            sx1[m] = bx.x; sy1[m] = bx.y; sx2[m] = bx.z; sy2[m] = bx.w;
            float ox1 = __fadd_rn(bx.x, offc), oy1 = __fadd_rn(bx.y, offc);
            float ox2 = __fadd_rn(bx.z, offc), oy2 = __fadd_rn(bx.w, offc);
            sar[m] = __fmul_rn(__fsub_rn(ox2, ox1), __fsub_rn(oy2, oy1));
        }
        __syncthreads();

        // ---- Stage 3: pairwise IoU>thr bit-matrix ----
        int W = (M + 31) >> 5;
        for (int i = wid; i < M; i += 4) {
            float ix1 = __fadd_rn(sx1[i], offc), iy1 = __fadd_rn(sy1[i], offc);
            float ix2 = __fadd_rn(sx2[i], offc), iy2 = __fadd_rn(sy2[i], offc);
            float ai  = sar[i];
            for (int cw = 0; cw < W; cw++) {
                int j = cw * 32 + lane;
                bool s = false;
                if (j < M && j > i) {
                    float jx1 = __fadd_rn(sx1[j], offc), jy1 = __fadd_rn(sy1[j], offc);
                    float jx2 = __fadd_rn(sx2[j], offc), jy2 = __fadd_rn(sy2[j], offc);
                    float aj  = sar[j];
                    float ltx = fmaxf(ix1, jx1), lty = fmaxf(iy1, jy1);
                    float rbx = fminf(ix2, jx2), rby = fminf(iy2, jy2);
                    float w = fmaxf(__fsub_rn(rbx, ltx), 0.0f);
                    float h = fmaxf(__fsub_rn(rby, lty), 0.0f);
                    float inter = __fmul_rn(w, h);
                    float denom = __fadd_rn(__fsub_rn(__fadd_rn(ai, aj), inter), 1e-9f);
                    s = __fdiv_rn(inter, denom) > IOU_THRF;
                }
                unsigned int bal = __ballot_sync(0xffffffffu, s);
                if (lane == 0) smask[i * WSTRIDE + cw] = bal;
            }
        }
        __syncthreads();

        // ---- Stage 4a: greedy keep-mask scan (thread 0, smem only) ----
        if (t == 0) {
            unsigned int sup[WSTRIDE], keep[WSTRIDE];
            #pragma unroll
            for (int w = 0; w < WSTRIDE; w++) { sup[w] = 0; keep[w] = 0; }
            for (int i = 0; i < M; i++) {
                if ((sup[i >> 5] >> (i & 31)) & 1u) continue;
                keep[i >> 5] |= (1u << (i & 31));
                for (int w = 0; w < W; w++) sup[w] |= smask[i * WSTRIDE + w];
            }
            #pragma unroll
            for (int w = 0; w < WSTRIDE; w++) keepw[w] = keep[w];
        }
        __syncthreads();

        // ---- Stage 4b: write kept rows DIRECTLY to output at row spos ----
        for (int m = t; m < M; m += 128) {
            if ((keepw[m >> 5] >> (m & 31)) & 1u) {
                float* o = out + ((size_t)b * NN + spos[m]) * 6;
                o[0] = sx1[m]; o[1] = sy1[m]; o[2] = sx2[m]; o[3] = sy2[m];
                o[4] = scf[m]; o[5] = (float)c;
            }
        }
        return;
    }

    // ---- Fallback (M > CAP): in-order greedy (members already sorted) ------
    for (int m = t; m < M; m += 128) fsup[m] = 0;
    __syncthreads();
    for (int i = 0; i < M; i++) {
        if (fsup[i]) { __syncthreads(); continue; }   // uniform across block
        int pos = flist[i];
        float4 bi = g_sbox[b * NN + pos];
        float ix1 = __fadd_rn(bi.x, offc), iy1 = __fadd_rn(bi.y, offc);
        float ix2 = __fadd_rn(bi.z, offc), iy2 = __fadd_rn(bi.w, offc);
        float ai  = __fmul_rn(__fsub_rn(ix2, ix1), __fsub_rn(iy2, iy1));
        if (t == 0) {
            float* o = out + ((size_t)b * NN + pos) * 6;
            o[0] = bi.x; o[1] = bi.y; o[2] = bi.z; o[3] = bi.w;
            o[4] = g_sconf[b * NN + pos];
            o[5] = (float)c;
        }
        for (int j = i + 1 + t; j < M; j += 128) {
            if (fsup[j]) continue;
            int pj = flist[j];
            float4 bj = g_sbox[b * NN + pj];
            float jx1 = __fadd_rn(bj.x, offc), jy1 = __fadd_rn(bj.y, offc);
            float jx2 = __fadd_rn(bj.z, offc), jy2 = __fadd_rn(bj.w, offc);
            float aj  = __fmul_rn(__fsub_rn(jx2, jx1), __fsub_rn(jy2, jy1));
            float ltx = fmaxf(ix1, jx1), lty = fmaxf(iy1, jy1);
            float rbx = fminf(ix2, jx2), rby = fminf(iy2, jy2);
            float w = fmaxf(__fsub_rn(rbx, ltx), 0.0f);
            float h = fmaxf(__fsub_rn(rby, lty), 0.0f);
            float inter = __fmul_rn(w, h);
            float denom = __fadd_rn(__fsub_rn(__fadd_rn(ai, aj), inter), 1e-9f);
            if (__fdiv_rn(inter, denom) > IOU_THRF) fsup[j] = 1;
        }
        __syncthreads();
    }
}

// ------------------------- launch -------------------------------------------
extern "C" void kernel_launch(void* const* d_in, const int* in_sizes, int n_in,
                              void* d_out, int out_size) {
    const float *boxes = nullptr, *scores = nullptr, *preds = nullptr;
    for (int i = 0; i < n_in; i++) {
        if (in_sizes[i] == BN * 4)       boxes  = (const float*)d_in[i];
        else if (in_sizes[i] == BN)      scores = (const float*)d_in[i];
        else if (in_sizes[i] == BN * CC) preds  = (const float*)d_in[i];
    }
    float* out = (float*)d_out;

    k1_prepare<<<(BN * 32) / 1024, 1024>>>(boxes, scores, preds);
    k2a_chunksort<<<BB * NCH, 128>>>();
    k2m_merge<<<BB * NCH, CHUNK>>>(out);
    k3_nms<<<BB * CC, 128>>>(out);
}

// round 10
// speedup vs baseline: 1.3880x; 1.0491x over previous
#include <cuda_runtime.h>
#include <cuda_bf16.h>
#include <cstdint>

// Problem constants
#define BB 4
#define NN 4096
#define CC 64
#define BN (BB * NN)
#define CHUNK 512
#define NCH (NN / CHUNK)          // 8 chunks per batch

#define TARGETF 560.0f
#define MIN_BOXF 5.0f
#define IOU_THRF 0.2f
#define CONF_THRF 0.001f
#define BOX_CONF_THRF 0.01f
#define MAX_WHF 4096.0f

#define CAP 256                    // per-class member cap for fast path
#define WSTRIDE 8                  // mask words per row (CAP/32)

// ------------------------- scratch (static device memory) -------------------
__device__ float4 g_cbox[BN];                      // clipped boxes, orig order
__device__ float  g_key[BN];                       // valid ? conf : -1
__device__ __align__(128) unsigned char g_tag[BN]; // valid ? cls : 255
__device__ unsigned long long g_ck[BN];            // sorted key chunks
__device__ float4 g_sbox[BN];                      // boxes in sorted order
__device__ float  g_sconf[BN];                     // conf in sorted order
__device__ __align__(128) unsigned char g_stag[BN];// tags in sorted order

// ------------------------- K1: conf / argmax / clip / valid -----------------
__global__ void k1_prepare(const float* __restrict__ boxes,
                           const float* __restrict__ scores,
                           const float* __restrict__ preds) {
    int box  = (blockIdx.x * blockDim.x + threadIdx.x) >> 5;
    int lane = threadIdx.x & 31;
    if (box >= BN) return;

    const float* p = preds + (size_t)box * CC;
    float s = scores[box];

    float v0 = __fmul_rn(p[lane], s);
    float v1 = __fmul_rn(p[lane + 32], s);
    float bv; int bi;
    if (v1 > v0) { bv = v1; bi = lane + 32; } else { bv = v0; bi = lane; }

    #pragma unroll
    for (int o = 16; o > 0; o >>= 1) {
        float ov = __shfl_down_sync(0xffffffffu, bv, o);
        int   oi = __shfl_down_sync(0xffffffffu, bi, o);
        if (ov > bv || (ov == bv && oi < bi)) { bv = ov; bi = oi; }
    }

    if (lane == 0) {
        float4 bx = reinterpret_cast<const float4*>(boxes)[box];
        float x1 = fminf(fmaxf(bx.x, 0.0f), TARGETF);
        float y1 = fminf(fmaxf(bx.y, 0.0f), TARGETF);
        float x2 = fminf(fmaxf(bx.z, 0.0f), TARGETF);
        float y2 = fminf(fmaxf(bx.w, 0.0f), TARGETF);
        float w = __fsub_rn(x2, x1);
        float h = __fsub_rn(y2, y1);
        int valid = (s > BOX_CONF_THRF) && (w > MIN_BOXF) && (h > MIN_BOXF)
                    && (bv > CONF_THRF);
        g_cbox[box] = make_float4(x1, y1, x2, y2);
        g_key[box]  = valid ? bv : -1.0f;
        g_tag[box]  = valid ? (unsigned char)bi : (unsigned char)255;
    }
}

// ------------------------- register bitonic helpers -------------------------
__device__ __forceinline__ unsigned long long kmin(unsigned long long a,
                                                   unsigned long long b) {
    return a < b ? a : b;
}
__device__ __forceinline__ unsigned long long kmax(unsigned long long a,
                                                   unsigned long long b) {
    return a > b ? a : b;
}
__device__ __forceinline__ void stage_j(unsigned long long v[4], int i0,
                                        int lane, int k, int j) {
    if (j >= 4) {
        int m = j >> 2;
        #pragma unroll
        for (int r = 0; r < 4; r++) {
            unsigned long long other = __shfl_xor_sync(0xffffffffu, v[r], m);
            bool up = (((i0 + r) & k) == 0);
            bool keepmin = (((lane & m) == 0) == up);
            v[r] = keepmin ? kmin(v[r], other) : kmax(v[r], other);
        }
    } else if (j == 2) {
        #pragma unroll
        for (int r = 0; r < 2; r++) {
            bool up = (((i0 + r) & k) == 0);
            unsigned long long a = v[r], c = v[r + 2];
            if ((a > c) == up) { v[r] = c; v[r + 2] = a; }
        }
    } else {
        #pragma unroll
        for (int r = 0; r < 4; r += 2) {
            bool up = (((i0 + r) & k) == 0);
            unsigned long long a = v[r], c = v[r + 1];
            if ((a > c) == up) { v[r] = c; v[r + 1] = a; }
        }
    }
}

// ------------------------- K2a: chunk sort (512 keys/block) -----------------
__global__ void __launch_bounds__(128) k2a_chunksort() {
    int b  = blockIdx.x >> 3;
    int ch = blockIdx.x & 7;
    __shared__ unsigned long long sk[CHUNK];
    int tid  = threadIdx.x;
    int lane = tid & 31;
    int i0   = ((tid >> 5) << 7) + (lane << 2);

    #pragma unroll
    for (int u = 0; u < 4; u++) {
        int i   = tid + u * 128;
        int idx = ch * CHUNK + i;
        unsigned int x = __float_as_uint(g_key[b * NN + idx]);
        x = (x & 0x80000000u) ? ~x : (x | 0x80000000u);
        sk[i] = ((unsigned long long)(~x) << 32) | (unsigned int)idx;
    }
    __syncthreads();

    // Phase A: k = 2..128 in registers
    {
        unsigned long long v[4];
        #pragma unroll
        for (int r = 0; r < 4; r++) v[r] = sk[i0 + r];
        #pragma unroll
        for (int k = 2; k <= 128; k <<= 1)
            for (int j = k >> 1; j >= 1; j >>= 1)
                stage_j(v, i0, lane, k, j);
        #pragma unroll
        for (int r = 0; r < 4; r++) sk[i0 + r] = v[r];
    }
    __syncthreads();

    // Phase B: k = 256, 512
    #pragma unroll
    for (int k = 256; k <= CHUNK; k <<= 1) {
        for (int j = k >> 1; j >= 128; j >>= 1) {
            #pragma unroll 2
            for (int u = 0; u < 2; u++) {
                int p   = tid + u * 128;
                int i   = ((p & ~(j - 1)) << 1) | (p & (j - 1));
                int ixj = i | j;
                bool up = ((i & k) == 0);
                unsigned long long a = sk[i], c = sk[ixj];
                if ((a > c) == up) { sk[i] = c; sk[ixj] = a; }
            }
            __syncthreads();
        }
        {
            unsigned long long v[4];
            #pragma unroll
            for (int r = 0; r < 4; r++) v[r] = sk[i0 + r];
            #pragma unroll
            for (int j = 64; j >= 1; j >>= 1)
                stage_j(v, i0, lane, k, j);
            #pragma unroll
            for (int r = 0; r < 4; r++) sk[i0 + r] = v[r];
        }
        __syncthreads();
    }

    #pragma unroll
    for (int u = 0; u < 4; u++) {
        int i = tid + u * 128;
        g_ck[b * NN + ch * CHUNK + i] = sk[i];
    }
}

// ------------------------- K2m: smem rank-merge + scatter + zero-out --------
// All 4096 batch keys staged to smem (one coalesced load); binary searches
// run at LDS latency with MLP=7. Each thread owns exactly one (batch, rank)
// output row, so it also zeroes that row (k0 deleted).
__global__ void __launch_bounds__(CHUNK) k2m_merge(float* __restrict__ out) {
    int b  = blockIdx.x >> 3;
    int ch = blockIdx.x & 7;
    int tid = threadIdx.x;

    __shared__ unsigned long long sck[NN];          // 32KB
    const unsigned long long* ck = g_ck + b * NN;
    #pragma unroll
    for (int u = 0; u < NCH; u++) sck[tid + u * CHUNK] = ck[tid + u * CHUNK];
    __syncthreads();

    unsigned long long K = sck[ch * CHUNK + tid];
    int rank = tid;

    int lo[NCH], hi[NCH];
    #pragma unroll
    for (int c2 = 0; c2 < NCH; c2++) { lo[c2] = 0; hi[c2] = (c2 == ch) ? 0 : CHUNK; }

    #pragma unroll
    for (int it = 0; it < 10; it++) {
        #pragma unroll
        for (int c2 = 0; c2 < NCH; c2++) {
            if (lo[c2] < hi[c2]) {
                int mid = (lo[c2] + hi[c2]) >> 1;
                unsigned long long v = sck[c2 * CHUNK + mid];
                if (v < K) lo[c2] = mid + 1; else hi[c2] = mid;
            }
        }
    }
    #pragma unroll
    for (int c2 = 0; c2 < NCH; c2++) rank += lo[c2];

    int idx = (int)(K & 0xffffffffull);
    int d = b * NN + rank;
    int s = b * NN + idx;

    // zero this thread's unique output row (poisoned by harness)
    float* o = out + (size_t)d * 6;
    o[0] = 0.0f; o[1] = 0.0f; o[2] = 0.0f;
    o[3] = 0.0f; o[4] = 0.0f; o[5] = 0.0f;

    g_sbox[d] = g_cbox[s];
    g_stag[d] = g_tag[s];
    // exact inverse of the total-order map -> original conf bits
    unsigned int up = ~(unsigned int)(K >> 32);
    unsigned int u  = (up & 0x80000000u) ? (up & 0x7fffffffu) : ~up;
    g_sconf[d] = __uint_as_float(u);
}

// ------------------------- K3: per-(batch,class) NMS on sorted arrays -------
__global__ void __launch_bounds__(128) k3_nms(float* __restrict__ out) {
    int bc   = blockIdx.x;
    int b    = bc >> 6;
    int c    = bc & 63;
    int t    = threadIdx.x;
    int lane = t & 31;
    int wid  = t >> 5;

    __shared__ float sx1[CAP], sy1[CAP], sx2[CAP], sy2[CAP];  // 4KB
    __shared__ float sar[CAP], scf[CAP];                      // 2KB
    __shared__ int   spos[CAP];                               // 1KB
    __shared__ unsigned int smask[CAP * WSTRIDE];             // 8KB
    __shared__ int   flist[NN];                               // 16KB
    __shared__ unsigned char fsup[NN];                        // 4KB (fallback)
    __shared__ int   warp_tot[5];
    __shared__ unsigned int keepw[WSTRIDE];

    // ---- Stage 1: compaction over SORTED tags ----
    const uint4* tw = reinterpret_cast<const uint4*>(g_stag + b * NN);
    uint4 wa = tw[t * 2], wb = tw[t * 2 + 1];
    unsigned int cls4 = (unsigned int)c * 0x01010101u;
    unsigned int eq[8];
    eq[0] = __vcmpeq4(wa.x, cls4); eq[1] = __vcmpeq4(wa.y, cls4);
    eq[2] = __vcmpeq4(wa.z, cls4); eq[3] = __vcmpeq4(wa.w, cls4);
    eq[4] = __vcmpeq4(wb.x, cls4); eq[5] = __vcmpeq4(wb.y, cls4);
    eq[6] = __vcmpeq4(wb.z, cls4); eq[7] = __vcmpeq4(wb.w, cls4);
    int cnt = 0;
    #pragma unroll
    for (int w = 0; w < 8; w++) cnt += __popc(eq[w]) >> 3;

    int inc = cnt;
    #pragma unroll
    for (int o = 1; o < 32; o <<= 1) {
        int tmp = __shfl_up_sync(0xffffffffu, inc, o);
        if (lane >= o) inc += tmp;
    }
    if (lane == 31) warp_tot[wid] = inc;
    __syncthreads();
    if (t == 0) {
        int run = 0;
        #pragma unroll
        for (int w = 0; w < 4; w++) { int v = warp_tot[w]; warp_tot[w] = run; run += v; }
        warp_tot[4] = run;
    }
    __syncthreads();
    int off = (inc - cnt) + warp_tot[wid];
    int base = t * 32;
    #pragma unroll
    for (int w = 0; w < 8; w++) {
        #pragma unroll
        for (int q = 0; q < 4; q++)
            if ((eq[w] >> (8 * q)) & 1u) flist[off++] = base + w * 4 + q;
    }
    __syncthreads();
    int M = warp_tot[4];
    if (M == 0) return;

    float offc = (float)c * MAX_WHF;   // exact in fp32

    if (M <= CAP) {
        // ---- Stage 2: gather member boxes (already in NMS order) ----
        for (int m = t; m < M; m += 128) {
            int pos = flist[m];
            spos[m] = pos;
            scf[m]  = g_sconf[b * NN + pos];
            float4 bx = g_sbox[b * NN + pos];
            sx1[m] = bx.x; sy1[m] = bx.y; sx2[m] = bx.z; sy2[m] = bx.w;
            float ox1 = __fadd_rn(bx.x, offc), oy1 = __fadd_rn(bx.y, offc);
            float ox2 = __fadd_rn(bx.z, offc), oy2 = __fadd_rn(bx.w, offc);
            sar[m] = __fmul_rn(__fsub_rn(ox2, ox1), __fsub_rn(oy2, oy1));
        }
        __syncthreads();

        // ---- Stage 3: pairwise IoU>thr bit-matrix ----
        int W = (M + 31) >> 5;
        for (int i = wid; i < M; i += 4) {
            float ix1 = __fadd_rn(sx1[i], offc), iy1 = __fadd_rn(sy1[i], offc);
            float ix2 = __fadd_rn(sx2[i], offc), iy2 = __fadd_rn(sy2[i], offc);
            float ai  = sar[i];
            for (int cw = 0; cw < W; cw++) {
                int j = cw * 32 + lane;
                bool s = false;
                if (j < M && j > i) {
                    float jx1 = __fadd_rn(sx1[j], offc), jy1 = __fadd_rn(sy1[j], offc);
                    float jx2 = __fadd_rn(sx2[j], offc), jy2 = __fadd_rn(sy2[j], offc);
                    float aj  = sar[j];
                    float ltx = fmaxf(ix1, jx1), lty = fmaxf(iy1, jy1);
                    float rbx = fminf(ix2, jx2), rby = fminf(iy2, jy2);
                    float w = fmaxf(__fsub_rn(rbx, ltx), 0.0f);
                    float h = fmaxf(__fsub_rn(rby, lty), 0.0f);
                    float inter = __fmul_rn(w, h);
                    float denom = __fadd_rn(__fsub_rn(__fadd_rn(ai, aj), inter), 1e-9f);
                    s = __fdiv_rn(inter, denom) > IOU_THRF;
                }
                unsigned int bal = __ballot_sync(0xffffffffu, s);
                if (lane == 0) smask[i * WSTRIDE + cw] = bal;
            }
        }
        __syncthreads();

        // ---- Stage 4a: greedy keep-mask scan (thread 0, smem only) ----
        if (t == 0) {
            unsigned int sup[WSTRIDE], keep[WSTRIDE];
            #pragma unroll
            for (int w = 0; w < WSTRIDE; w++) { sup[w] = 0; keep[w] = 0; }
            for (int i = 0; i < M; i++) {
                if ((sup[i >> 5] >> (i & 31)) & 1u) continue;
                keep[i >> 5] |= (1u << (i & 31));
                for (int w = 0; w < W; w++) sup[w] |= smask[i * WSTRIDE + w];
            }
            #pragma unroll
            for (int w = 0; w < WSTRIDE; w++) keepw[w] = keep[w];
        }
        __syncthreads();

        // ---- Stage 4b: write kept rows DIRECTLY to output at row spos ----
        for (int m = t; m < M; m += 128) {
            if ((keepw[m >> 5] >> (m & 31)) & 1u) {
                float* o = out + ((size_t)b * NN + spos[m]) * 6;
                o[0] = sx1[m]; o[1] = sy1[m]; o[2] = sx2[m]; o[3] = sy2[m];
                o[4] = scf[m]; o[5] = (float)c;
            }
        }
        return;
    }

    // ---- Fallback (M > CAP): in-order greedy (members already sorted) ------
    for (int m = t; m < M; m += 128) fsup[m] = 0;
    __syncthreads();
    for (int i = 0; i < M; i++) {
        if (fsup[i]) { __syncthreads(); continue; }   // uniform across block
        int pos = flist[i];
        float4 bi = g_sbox[b * NN + pos];
        float ix1 = __fadd_rn(bi.x, offc), iy1 = __fadd_rn(bi.y, offc);
        float ix2 = __fadd_rn(bi.z, offc), iy2 = __fadd_rn(bi.w, offc);
        float ai  = __fmul_rn(__fsub_rn(ix2, ix1), __fsub_rn(iy2, iy1));
        if (t == 0) {
            float* o = out + ((size_t)b * NN + pos) * 6;
            o[0] = bi.x; o[1] = bi.y; o[2] = bi.z; o[3] = bi.w;
            o[4] = g_sconf[b * NN + pos];
            o[5] = (float)c;
        }
        for (int j = i + 1 + t; j < M; j += 128) {
            if (fsup[j]) continue;
            int pj = flist[j];
            float4 bj = g_sbox[b * NN + pj];
            float jx1 = __fadd_rn(bj.x, offc), jy1 = __fadd_rn(bj.y, offc);
            float jx2 = __fadd_rn(bj.z, offc), jy2 = __fadd_rn(bj.w, offc);
            float aj  = __fmul_rn(__fsub_rn(jx2, jx1), __fsub_rn(jy2, jy1));
            float ltx = fmaxf(ix1, jx1), lty = fmaxf(iy1, jy1);
            float rbx = fminf(ix2, jx2), rby = fminf(iy2, jy2);
            float w = fmaxf(__fsub_rn(rbx, ltx), 0.0f);
            float h = fmaxf(__fsub_rn(rby, lty), 0.0f);
            float inter = __fmul_rn(w, h);
            float denom = __fadd_rn(__fsub_rn(__fadd_rn(ai, aj), inter), 1e-9f);
            if (__fdiv_rn(inter, denom) > IOU_THRF) fsup[j] = 1;
        }
        __syncthreads();
    }
}

// ------------------------- launch -------------------------------------------
extern "C" void kernel_launch(void* const* d_in, const int* in_sizes, int n_in,
                              void* d_out, int out_size) {
    const float *boxes = nullptr, *scores = nullptr, *preds = nullptr;
    for (int i = 0; i < n_in; i++) {
        if (in_sizes[i] == BN * 4)       boxes  = (const float*)d_in[i];
        else if (in_sizes[i] == BN)      scores = (const float*)d_in[i];
        else if (in_sizes[i] == BN * CC) preds  = (const float*)d_in[i];
    }
    float* out = (float*)d_out;

    k1_prepare<<<(BN * 32) / 1024, 1024>>>(boxes, scores, preds);
    k2a_chunksort<<<BB * NCH, 128>>>();
    k2m_merge<<<BB * NCH, CHUNK>>>(out);
    k3_nms<<<BB * CC, 128>>>(out);
}

// round 11
// speedup vs baseline: 1.8713x; 1.3481x over previous
#include <cuda_runtime.h>
#include <cuda_bf16.h>
#include <cstdint>

// Problem constants
#define BB 4
#define NN 4096
#define CC 64
#define BN (BB * NN)
#define CHUNK 512
#define NCH (NN / CHUNK)          // 8 chunks per batch

#define TARGETF 560.0f
#define MIN_BOXF 5.0f
#define IOU_THRF 0.2f
#define CONF_THRF 0.001f
#define BOX_CONF_THRF 0.01f
#define MAX_WHF 4096.0f

#define CAP 256                    // per-class member cap for fast path
#define WSTRIDE 8                  // mask words per row (CAP/32)

// ------------------------- scratch (static device memory) -------------------
__device__ float4 g_cbox[BN];                      // clipped boxes, orig order
__device__ float  g_key[BN];                       // valid ? conf : -1
__device__ __align__(128) unsigned char g_tag[BN]; // valid ? cls : 255
__device__ unsigned long long g_ck[BN];            // sorted key chunks
__device__ float4 g_sbox[BN];                      // boxes in sorted order
__device__ float  g_sconf[BN];                     // conf in sorted order
__device__ __align__(128) unsigned char g_stag[BN];// tags in sorted order

// ------------------------- K1: conf / argmax / clip / valid -----------------
__global__ void k1_prepare(const float* __restrict__ boxes,
                           const float* __restrict__ scores,
                           const float* __restrict__ preds) {
    int box  = (blockIdx.x * blockDim.x + threadIdx.x) >> 5;
    int lane = threadIdx.x & 31;
    if (box >= BN) return;

    const float* p = preds + (size_t)box * CC;
    float s = scores[box];

    float v0 = __fmul_rn(p[lane], s);
    float v1 = __fmul_rn(p[lane + 32], s);
    float bv; int bi;
    if (v1 > v0) { bv = v1; bi = lane + 32; } else { bv = v0; bi = lane; }

    #pragma unroll
    for (int o = 16; o > 0; o >>= 1) {
        float ov = __shfl_down_sync(0xffffffffu, bv, o);
        int   oi = __shfl_down_sync(0xffffffffu, bi, o);
        if (ov > bv || (ov == bv && oi < bi)) { bv = ov; bi = oi; }
    }

    if (lane == 0) {
        float4 bx = reinterpret_cast<const float4*>(boxes)[box];
        float x1 = fminf(fmaxf(bx.x, 0.0f), TARGETF);
        float y1 = fminf(fmaxf(bx.y, 0.0f), TARGETF);
        float x2 = fminf(fmaxf(bx.z, 0.0f), TARGETF);
        float y2 = fminf(fmaxf(bx.w, 0.0f), TARGETF);
        float w = __fsub_rn(x2, x1);
        float h = __fsub_rn(y2, y1);
        int valid = (s > BOX_CONF_THRF) && (w > MIN_BOXF) && (h > MIN_BOXF)
                    && (bv > CONF_THRF);
        g_cbox[box] = make_float4(x1, y1, x2, y2);
        g_key[box]  = valid ? bv : -1.0f;
        g_tag[box]  = valid ? (unsigned char)bi : (unsigned char)255;
    }
}

// ------------------------- register bitonic helpers -------------------------
__device__ __forceinline__ unsigned long long kmin(unsigned long long a,
                                                   unsigned long long b) {
    return a < b ? a : b;
}
__device__ __forceinline__ unsigned long long kmax(unsigned long long a,
                                                   unsigned long long b) {
    return a > b ? a : b;
}
__device__ __forceinline__ void stage_j(unsigned long long v[4], int i0,
                                        int lane, int k, int j) {
    if (j >= 4) {
        int m = j >> 2;
        #pragma unroll
        for (int r = 0; r < 4; r++) {
            unsigned long long other = __shfl_xor_sync(0xffffffffu, v[r], m);
            bool up = (((i0 + r) & k) == 0);
            bool keepmin = (((lane & m) == 0) == up);
            v[r] = keepmin ? kmin(v[r], other) : kmax(v[r], other);
        }
    } else if (j == 2) {
        #pragma unroll
        for (int r = 0; r < 2; r++) {
            bool up = (((i0 + r) & k) == 0);
            unsigned long long a = v[r], c = v[r + 2];
            if ((a > c) == up) { v[r] = c; v[r + 2] = a; }
        }
    } else {
        #pragma unroll
        for (int r = 0; r < 4; r += 2) {
            bool up = (((i0 + r) & k) == 0);
            unsigned long long a = v[r], c = v[r + 1];
            if ((a > c) == up) { v[r] = c; v[r + 1] = a; }
        }
    }
}

// ------------------------- K2a: chunk sort (512 keys/block) -----------------
__global__ void __launch_bounds__(128) k2a_chunksort() {
    int b  = blockIdx.x >> 3;
    int ch = blockIdx.x & 7;
    __shared__ unsigned long long sk[CHUNK];
    int tid  = threadIdx.x;
    int lane = tid & 31;
    int i0   = ((tid >> 5) << 7) + (lane << 2);

    #pragma unroll
    for (int u = 0; u < 4; u++) {
        int i   = tid + u * 128;
        int idx = ch * CHUNK + i;
        unsigned int x = __float_as_uint(g_key[b * NN + idx]);
        x = (x & 0x80000000u) ? ~x : (x | 0x80000000u);
        sk[i] = ((unsigned long long)(~x) << 32) | (unsigned int)idx;
    }
    __syncthreads();

    {
        unsigned long long v[4];
        #pragma unroll
        for (int r = 0; r < 4; r++) v[r] = sk[i0 + r];
        #pragma unroll
        for (int k = 2; k <= 128; k <<= 1)
            for (int j = k >> 1; j >= 1; j >>= 1)
                stage_j(v, i0, lane, k, j);
        #pragma unroll
        for (int r = 0; r < 4; r++) sk[i0 + r] = v[r];
    }
    __syncthreads();

    #pragma unroll
    for (int k = 256; k <= CHUNK; k <<= 1) {
        for (int j = k >> 1; j >= 128; j >>= 1) {
            #pragma unroll 2
            for (int u = 0; u < 2; u++) {
                int p   = tid + u * 128;
                int i   = ((p & ~(j - 1)) << 1) | (p & (j - 1));
                int ixj = i | j;
                bool up = ((i & k) == 0);
                unsigned long long a = sk[i], c = sk[ixj];
                if ((a > c) == up) { sk[i] = c; sk[ixj] = a; }
            }
            __syncthreads();
        }
        {
            unsigned long long v[4];
            #pragma unroll
            for (int r = 0; r < 4; r++) v[r] = sk[i0 + r];
            #pragma unroll
            for (int j = 64; j >= 1; j >>= 1)
                stage_j(v, i0, lane, k, j);
            #pragma unroll
            for (int r = 0; r < 4; r++) sk[i0 + r] = v[r];
        }
        __syncthreads();
    }

    #pragma unroll
    for (int u = 0; u < 4; u++) {
        int i = tid + u * 128;
        g_ck[b * NN + ch * CHUNK + i] = sk[i];
    }
}

// ------------------------- K2m: smem rank-merge + scatter + zero-out --------
__global__ void __launch_bounds__(CHUNK) k2m_merge(float* __restrict__ out) {
    int b  = blockIdx.x >> 3;
    int ch = blockIdx.x & 7;
    int tid = threadIdx.x;

    __shared__ unsigned long long sck[NN];          // 32KB
    const unsigned long long* ck = g_ck + b * NN;
    #pragma unroll
    for (int u = 0; u < NCH; u++) sck[tid + u * CHUNK] = ck[tid + u * CHUNK];
    __syncthreads();

    unsigned long long K = sck[ch * CHUNK + tid];
    int rank = tid;

    int lo[NCH], hi[NCH];
    #pragma unroll
    for (int c2 = 0; c2 < NCH; c2++) { lo[c2] = 0; hi[c2] = (c2 == ch) ? 0 : CHUNK; }

    #pragma unroll
    for (int it = 0; it < 10; it++) {
        #pragma unroll
        for (int c2 = 0; c2 < NCH; c2++) {
            if (lo[c2] < hi[c2]) {
                int mid = (lo[c2] + hi[c2]) >> 1;
                unsigned long long v = sck[c2 * CHUNK + mid];
                if (v < K) lo[c2] = mid + 1; else hi[c2] = mid;
            }
        }
    }
    #pragma unroll
    for (int c2 = 0; c2 < NCH; c2++) rank += lo[c2];

    int idx = (int)(K & 0xffffffffull);
    int d = b * NN + rank;
    int s = b * NN + idx;

    float* o = out + (size_t)d * 6;
    o[0] = 0.0f; o[1] = 0.0f; o[2] = 0.0f;
    o[3] = 0.0f; o[4] = 0.0f; o[5] = 0.0f;

    g_sbox[d] = g_cbox[s];
    g_stag[d] = g_tag[s];
    unsigned int up = ~(unsigned int)(K >> 32);
    unsigned int u  = (up & 0x80000000u) ? (up & 0x7fffffffu) : ~up;
    g_sconf[d] = __uint_as_float(u);
}

// ------------------------- K3: per-(batch,class) NMS on sorted arrays -------
// 256 threads. Compaction over sorted tags -> bit-matrix (upper triangle
// words only) -> warp-cooperative ffs greedy -> direct output writes.
__global__ void __launch_bounds__(256) k3_nms(float* __restrict__ out) {
    int bc   = blockIdx.x;
    int b    = bc >> 6;
    int c    = bc & 63;
    int t    = threadIdx.x;
    int lane = t & 31;
    int wid  = t >> 5;

    __shared__ float sx1[CAP], sy1[CAP], sx2[CAP], sy2[CAP];  // 4KB
    __shared__ float sar[CAP], scf[CAP];                      // 2KB
    __shared__ int   spos[CAP];                               // 1KB
    __shared__ unsigned int smask[CAP * WSTRIDE];             // 8KB
    __shared__ int   flist[CAP];                              // 1KB
    __shared__ unsigned short mb[256];                        // membership bitmap
    __shared__ unsigned short supb[256];                      // fallback suppress
    __shared__ int   warp_tot[9];
    __shared__ unsigned int keepw[WSTRIDE];

    // ---- Stage 1: compaction over SORTED tags (16 tags/thread) ----
    const uint4* tw = reinterpret_cast<const uint4*>(g_stag + b * NN);
    uint4 wa = tw[t];
    unsigned int cls4 = (unsigned int)c * 0x01010101u;
    unsigned int eq[4];
    eq[0] = __vcmpeq4(wa.x, cls4); eq[1] = __vcmpeq4(wa.y, cls4);
    eq[2] = __vcmpeq4(wa.z, cls4); eq[3] = __vcmpeq4(wa.w, cls4);
    int cnt = 0;
    unsigned int mbv = 0;
    #pragma unroll
    for (int w = 0; w < 4; w++) {
        cnt += __popc(eq[w]) >> 3;
        #pragma unroll
        for (int q = 0; q < 4; q++)
            if ((eq[w] >> (8 * q)) & 1u) mbv |= 1u << (w * 4 + q);
    }
    mb[t] = (unsigned short)mbv;

    int inc = cnt;
    #pragma unroll
    for (int o = 1; o < 32; o <<= 1) {
        int tmp = __shfl_up_sync(0xffffffffu, inc, o);
        if (lane >= o) inc += tmp;
    }
    if (lane == 31) warp_tot[wid] = inc;
    __syncthreads();
    if (t == 0) {
        int run = 0;
        #pragma unroll
        for (int w = 0; w < 8; w++) { int v = warp_tot[w]; warp_tot[w] = run; run += v; }
        warp_tot[8] = run;
    }
    __syncthreads();
    int off = (inc - cnt) + warp_tot[wid];
    int base = t * 16;
    #pragma unroll
    for (int q = 0; q < 16; q++) {
        if ((mbv >> q) & 1u) {
            if (off < CAP) flist[off] = base + q;
            off++;
        }
    }
    __syncthreads();
    int M = warp_tot[8];
    if (M == 0) return;

    float offc = (float)c * MAX_WHF;   // exact in fp32

    if (M <= CAP) {
        // ---- Stage 2: gather member boxes (already in NMS order) ----
        for (int m = t; m < M; m += 256) {
            int pos = flist[m];
            spos[m] = pos;
            scf[m]  = g_sconf[b * NN + pos];
            float4 bx = g_sbox[b * NN + pos];
            sx1[m] = bx.x; sy1[m] = bx.y; sx2[m] = bx.z; sy2[m] = bx.w;
            float ox1 = __fadd_rn(bx.x, offc), oy1 = __fadd_rn(bx.y, offc);
            float ox2 = __fadd_rn(bx.z, offc), oy2 = __fadd_rn(bx.w, offc);
            sar[m] = __fmul_rn(__fsub_rn(ox2, ox1), __fsub_rn(oy2, oy1));
        }
        __syncthreads();

        // ---- Stage 3: pairwise IoU>thr bit-matrix (upper-triangle words) ----
        int W = (M + 31) >> 5;
        for (int i = wid; i < M; i += 8) {
            float ix1 = __fadd_rn(sx1[i], offc), iy1 = __fadd_rn(sy1[i], offc);
            float ix2 = __fadd_rn(sx2[i], offc), iy2 = __fadd_rn(sy2[i], offc);
            float ai  = sar[i];
            for (int cw = (i >> 5); cw < W; cw++) {
                int j = cw * 32 + lane;
                bool s = false;
                if (j < M && j > i) {
                    float jx1 = __fadd_rn(sx1[j], offc), jy1 = __fadd_rn(sy1[j], offc);
                    float jx2 = __fadd_rn(sx2[j], offc), jy2 = __fadd_rn(sy2[j], offc);
                    float aj  = sar[j];
                    float ltx = fmaxf(ix1, jx1), lty = fmaxf(iy1, jy1);
                    float rbx = fminf(ix2, jx2), rby = fminf(iy2, jy2);
                    float w = fmaxf(__fsub_rn(rbx, ltx), 0.0f);
                    float h = fmaxf(__fsub_rn(rby, lty), 0.0f);
                    float inter = __fmul_rn(w, h);
                    float denom = __fadd_rn(__fsub_rn(__fadd_rn(ai, aj), inter), 1e-9f);
                    s = __fdiv_rn(inter, denom) > IOU_THRF;
                }
                unsigned int bal = __ballot_sync(0xffffffffu, s);
                if (lane == 0) smask[i * WSTRIDE + cw] = bal;
            }
        }
        __syncthreads();

        // ---- Stage 4a: warp-cooperative ffs greedy (warp 0) ----
        if (wid == 0) {
            int W2 = (M + 31) >> 5;
            unsigned int rem = 0;
            if (lane < W2) {
                int rb = M - lane * 32;
                rem = (rb >= 32) ? 0xffffffffu : ((1u << rb) - 1u);
            }
            unsigned int keep = 0;
            for (;;) {
                unsigned int bal = __ballot_sync(0xffffffffu, rem != 0);
                if (!bal) break;
                int src = __ffs(bal) - 1;
                unsigned int word = __shfl_sync(0xffffffffu, rem, src);
                int i = (src << 5) + __ffs(word) - 1;
                if (lane == src) {
                    keep |= 1u << (i & 31);
                    rem  &= ~(1u << (i & 31));
                }
                unsigned int supr = (lane < W2 && lane >= (i >> 5))
                                  ? smask[i * WSTRIDE + lane] : 0u;
                rem &= ~supr;
            }
            if (lane < WSTRIDE) keepw[lane] = (lane < W2) ? keep : 0u;
        }
        __syncthreads();

        // ---- Stage 4b: write kept rows DIRECTLY to output at row spos ----
        for (int m = t; m < M; m += 256) {
            if ((keepw[m >> 5] >> (m & 31)) & 1u) {
                float* o = out + ((size_t)b * NN + spos[m]) * 6;
                o[0] = sx1[m]; o[1] = sy1[m]; o[2] = sx2[m]; o[3] = sy2[m];
                o[4] = scf[m]; o[5] = (float)c;
            }
        }
        return;
    }

    // ---- Fallback (M > CAP): bitmap greedy in position order (never hit) ---
    supb[t] = 0;
    __syncthreads();
    for (int w = 0; w < 256; w++) {
        unsigned int avail = (unsigned int)(mb[w] & (unsigned short)~supb[w]);
        while (avail) {
            int bit = __ffs(avail) - 1;
            int pos = w * 16 + bit;
            float4 bi = g_sbox[b * NN + pos];
            float ix1 = __fadd_rn(bi.x, offc), iy1 = __fadd_rn(bi.y, offc);
            float ix2 = __fadd_rn(bi.z, offc), iy2 = __fadd_rn(bi.w, offc);
            float ai  = __fmul_rn(__fsub_rn(ix2, ix1), __fsub_rn(iy2, iy1));
            if (t == 0) {
                float* o = out + ((size_t)b * NN + pos) * 6;
                o[0] = bi.x; o[1] = bi.y; o[2] = bi.z; o[3] = bi.w;
                o[4] = g_sconf[b * NN + pos];
                o[5] = (float)c;
            }
            // each thread suppresses within its own 16 positions
            unsigned int mymb = mb[t], mysup = supb[t];
            #pragma unroll
            for (int q = 0; q < 16; q++) {
                int j = t * 16 + q;
                if (j > pos && ((mymb >> q) & 1u) && !((mysup >> q) & 1u)) {
                    float4 bj = g_sbox[b * NN + j];
                    float jx1 = __fadd_rn(bj.x, offc), jy1 = __fadd_rn(bj.y, offc);
                    float jx2 = __fadd_rn(bj.z, offc), jy2 = __fadd_rn(bj.w, offc);
                    float aj  = __fmul_rn(__fsub_rn(jx2, jx1), __fsub_rn(jy2, jy1));
                    float ltx = fmaxf(ix1, jx1), lty = fmaxf(iy1, jy1);
                    float rbx = fminf(ix2, jx2), rby = fminf(iy2, jy2);
                    float wq = fmaxf(__fsub_rn(rbx, ltx), 0.0f);
                    float hq = fmaxf(__fsub_rn(rby, lty), 0.0f);
                    float inter = __fmul_rn(wq, hq);
                    float denom = __fadd_rn(__fsub_rn(__fadd_rn(ai, aj), inter), 1e-9f);
                    if (__fdiv_rn(inter, denom) > IOU_THRF) mysup |= 1u << q;
                }
            }
            supb[t] = (unsigned short)mysup;
            __syncthreads();
            avail = (unsigned int)(mb[w] & (unsigned short)~supb[w]);
            avail &= ~((bit == 31) ? 0xffffffffu : ((1u << (bit + 1)) - 1u));
        }
        __syncthreads();
    }
}

// ------------------------- launch -------------------------------------------
extern "C" void kernel_launch(void* const* d_in, const int* in_sizes, int n_in,
                              void* d_out, int out_size) {
    const float *boxes = nullptr, *scores = nullptr, *preds = nullptr;
    for (int i = 0; i < n_in; i++) {
        if (in_sizes[i] == BN * 4)       boxes  = (const float*)d_in[i];
        else if (in_sizes[i] == BN)      scores = (const float*)d_in[i];
        else if (in_sizes[i] == BN * CC) preds  = (const float*)d_in[i];
    }
    float* out = (float*)d_out;

    k1_prepare<<<(BN * 32) / 1024, 1024>>>(boxes, scores, preds);
    k2a_chunksort<<<BB * NCH, 128>>>();
    k2m_merge<<<BB * NCH, CHUNK>>>(out);
    k3_nms<<<BB * CC, 256>>>(out);
}